// round 2
// baseline (speedup 1.0000x reference)
#include <cuda_runtime.h>
#include <cmath>

#define BATCH 2
#define CH    512
#define NPIX  4096
#define NGRP  32
#define CPG   16

// ---------------- scratch (device globals: allocation-free) ----------------
static __device__ float g_hn[(size_t)BATCH * CH * NPIX];
static __device__ float g_q [(size_t)BATCH * CH * NPIX];
static __device__ float g_k [(size_t)BATCH * CH * NPIX];
static __device__ float g_v [(size_t)BATCH * CH * NPIX];
static __device__ float g_o [(size_t)BATCH * CH * NPIX];
static __device__ float g_s [(size_t)BATCH * NPIX * NPIX];   // 134 MB scores/attn

__device__ __forceinline__ float* sel_ptr(int sel, const float* ext) {
    switch (sel) {
        case 1: return g_hn;
        case 2: return g_q;
        case 3: return g_k;
        case 4: return g_v;
        case 5: return g_s;
        case 6: return g_o;
        default: return (float*)ext;
    }
}

// ---------------- GroupNorm ----------------
__global__ void __launch_bounds__(256) groupnorm_kernel(
    const float* __restrict__ x, const float* __restrict__ gamma,
    const float* __restrict__ beta)
{
    const int g = blockIdx.x, b = blockIdx.y;
    const size_t base = ((size_t)b * CH + (size_t)g * CPG) * NPIX;
    const float4* x4 = (const float4*)(x + base);
    float4* hn4 = (float4*)(g_hn + base);
    const int n4 = CPG * NPIX / 4;   // 16384 float4s

    float s = 0.f, ss = 0.f;
    for (int i = threadIdx.x; i < n4; i += 256) {
        float4 v = x4[i];
        s  += v.x + v.y + v.z + v.w;
        ss += v.x * v.x + v.y * v.y + v.z * v.z + v.w * v.w;
    }
    __shared__ float rs[8], rss[8];
    __shared__ float s_mean, s_rstd;
    #pragma unroll
    for (int o = 16; o; o >>= 1) {
        s  += __shfl_xor_sync(0xffffffffu, s, o);
        ss += __shfl_xor_sync(0xffffffffu, ss, o);
    }
    const int lane = threadIdx.x & 31, wid = threadIdx.x >> 5;
    if (lane == 0) { rs[wid] = s; rss[wid] = ss; }
    __syncthreads();
    if (threadIdx.x == 0) {
        float ts = 0.f, tss = 0.f;
        #pragma unroll
        for (int i = 0; i < 8; i++) { ts += rs[i]; tss += rss[i]; }
        const float inv_n = 1.0f / (CPG * NPIX);
        float mean = ts * inv_n;
        float var = tss * inv_n - mean * mean;
        s_mean = mean;
        s_rstd = rsqrtf(var + 1e-6f);
    }
    __syncthreads();
    const float mean = s_mean, rstd = s_rstd;

    for (int i = threadIdx.x; i < n4; i += 256) {
        int c = g * CPG + (i >> 10);       // 1024 float4 per channel row
        float gm = gamma[c] * rstd;
        float bt = beta[c] - mean * gm;
        float4 v = x4[i];
        v.x = v.x * gm + bt;
        v.y = v.y * gm + bt;
        v.z = v.z * gm + bt;
        v.w = v.w * gm + bt;
        hn4[i] = v;
    }
}

// ---------------- Generic tiled fp32 GEMM ----------------
// C[m,n] = sum_k A[m,k]*B[k,n] with element strides (sa_m,sa_k),(sb_k,sb_n).
// A_K1: A's k-stride == 1 (vectorize along k).  B_N1: B's n-stride == 1.
// EPI: 0 none | 1 +bias[m] | 2 *scale | 3 +bias[m]+resid
template<bool A_K1, bool B_N1, int EPI>
__global__ void __launch_bounds__(256) gemm_kernel(
    const float* __restrict__ Aext, int Asel,
    const float* __restrict__ Bext, int Bsel,
    float* __restrict__ Cext, int Csel,
    int Ncols, int K,
    int sa_m, int sa_k, int sb_k, int sb_n,
    size_t Ab, size_t Bb, size_t Cb,
    const float* __restrict__ bias,
    const float* __restrict__ resid, size_t Rb,
    float scale)
{
    const int bz = blockIdx.z;
    const float* A = sel_ptr(Asel, Aext) + (size_t)bz * Ab;
    const float* B = sel_ptr(Bsel, Bext) + (size_t)bz * Bb;
    float* C = sel_ptr(Csel, (const float*)Cext) + (size_t)bz * Cb;

    const int m0 = blockIdx.y * 64, n0 = blockIdx.x * 64;
    __shared__ __align__(16) float As[16][68];
    __shared__ __align__(16) float Bs[16][68];

    const int tid = threadIdx.x;
    const int tx = tid & 15, ty = tid >> 4;

    float acc[4][4] = {};

    for (int k0 = 0; k0 < K; k0 += 16) {
        if (A_K1) {
            int m = tid >> 2;            // 0..63
            int kk = (tid & 3) * 4;      // 0,4,8,12
            float4 av = *(const float4*)&A[(size_t)(m0 + m) * sa_m + (k0 + kk)];
            As[kk + 0][m] = av.x; As[kk + 1][m] = av.y;
            As[kk + 2][m] = av.z; As[kk + 3][m] = av.w;
        } else {
            int kk = tid >> 4;           // 0..15
            int m = (tid & 15) * 4;
            float4 av = *(const float4*)&A[(size_t)(k0 + kk) * sa_k + (m0 + m)];
            *(float4*)&As[kk][m] = av;
        }
        if (B_N1) {
            int kk = tid >> 4;
            int n = (tid & 15) * 4;
            float4 bv = *(const float4*)&B[(size_t)(k0 + kk) * sb_k + (n0 + n)];
            *(float4*)&Bs[kk][n] = bv;
        } else {
            int n = tid >> 2;
            int kk = (tid & 3) * 4;
            float4 bv = *(const float4*)&B[(size_t)(n0 + n) * sb_n + (k0 + kk)];
            Bs[kk + 0][n] = bv.x; Bs[kk + 1][n] = bv.y;
            Bs[kk + 2][n] = bv.z; Bs[kk + 3][n] = bv.w;
        }
        __syncthreads();
        #pragma unroll
        for (int kk = 0; kk < 16; kk++) {
            float4 a = *(const float4*)&As[kk][ty * 4];
            float4 b = *(const float4*)&Bs[kk][tx * 4];
            acc[0][0] += a.x * b.x; acc[0][1] += a.x * b.y; acc[0][2] += a.x * b.z; acc[0][3] += a.x * b.w;
            acc[1][0] += a.y * b.x; acc[1][1] += a.y * b.y; acc[1][2] += a.y * b.z; acc[1][3] += a.y * b.w;
            acc[2][0] += a.z * b.x; acc[2][1] += a.z * b.y; acc[2][2] += a.z * b.z; acc[2][3] += a.z * b.w;
            acc[3][0] += a.w * b.x; acc[3][1] += a.w * b.y; acc[3][2] += a.w * b.z; acc[3][3] += a.w * b.w;
        }
        __syncthreads();
    }

    const int row = m0 + ty * 4;
    const int col = n0 + tx * 4;
    #pragma unroll
    for (int i = 0; i < 4; i++) {
        float4 o;
        o.x = acc[i][0]; o.y = acc[i][1]; o.z = acc[i][2]; o.w = acc[i][3];
        if (EPI == 2) { o.x *= scale; o.y *= scale; o.z *= scale; o.w *= scale; }
        if (EPI == 1 || EPI == 3) {
            float bv = bias[row + i];
            o.x += bv; o.y += bv; o.z += bv; o.w += bv;
        }
        if (EPI == 3) {
            float4 r = *(const float4*)&resid[(size_t)bz * Rb + (size_t)(row + i) * Ncols + col];
            o.x += r.x; o.y += r.y; o.z += r.z; o.w += r.w;
        }
        *(float4*)&C[(size_t)(row + i) * Ncols + col] = o;
    }
}

// ---------------- row softmax on g_s (in place, row resident in registers) ----
__global__ void __launch_bounds__(256) softmax_kernel()
{
    const size_t row = blockIdx.x;           // 0 .. BATCH*NPIX-1
    float4* p = (float4*)(g_s + row * (size_t)NPIX);
    const int t = threadIdx.x;
    float4 v[4];
    float mx = -1e30f;
    #pragma unroll
    for (int i = 0; i < 4; i++) {
        v[i] = p[t + 256 * i];
        mx = fmaxf(mx, fmaxf(fmaxf(v[i].x, v[i].y), fmaxf(v[i].z, v[i].w)));
    }
    __shared__ float red[8];
    const int lane = t & 31, wid = t >> 5;
    #pragma unroll
    for (int o = 16; o; o >>= 1) mx = fmaxf(mx, __shfl_xor_sync(0xffffffffu, mx, o));
    if (lane == 0) red[wid] = mx;
    __syncthreads();
    if (t == 0) {
        float m = red[0];
        #pragma unroll
        for (int i = 1; i < 8; i++) m = fmaxf(m, red[i]);
        red[0] = m;
    }
    __syncthreads();
    mx = red[0];
    __syncthreads();

    float sum = 0.f;
    #pragma unroll
    for (int i = 0; i < 4; i++) {
        v[i].x = __expf(v[i].x - mx);
        v[i].y = __expf(v[i].y - mx);
        v[i].z = __expf(v[i].z - mx);
        v[i].w = __expf(v[i].w - mx);
        sum += v[i].x + v[i].y + v[i].z + v[i].w;
    }
    #pragma unroll
    for (int o = 16; o; o >>= 1) sum += __shfl_xor_sync(0xffffffffu, sum, o);
    if (lane == 0) red[wid] = sum;
    __syncthreads();
    if (t == 0) {
        float s = 0.f;
        #pragma unroll
        for (int i = 0; i < 8; i++) s += red[i];
        red[0] = s;
    }
    __syncthreads();
    const float inv = 1.0f / red[0];
    #pragma unroll
    for (int i = 0; i < 4; i++) {
        v[i].x *= inv; v[i].y *= inv; v[i].z *= inv; v[i].w *= inv;
        p[t + 256 * i] = v[i];
    }
}

// ---------------- launcher ----------------
extern "C" void kernel_launch(void* const* d_in, const int* in_sizes, int n_in,
                              void* d_out, int out_size)
{
    const float* x     = (const float*)d_in[0];
    const float* gamma = (const float*)d_in[1];
    const float* beta  = (const float*)d_in[2];
    const float* Wq    = (const float*)d_in[3];
    const float* bq    = (const float*)d_in[4];
    const float* Wk    = (const float*)d_in[5];
    const float* bk    = (const float*)d_in[6];
    const float* Wv    = (const float*)d_in[7];
    const float* bv    = (const float*)d_in[8];
    const float* Wo    = (const float*)d_in[9];
    const float* bo    = (const float*)d_in[10];
    float* out = (float*)d_out;

    const size_t CN = (size_t)CH * NPIX;       // per-batch [C,N]
    const size_t NN = (size_t)NPIX * NPIX;     // per-batch [N,N]
    const float scale = 1.0f / sqrtf((float)CH);

    // 1) GroupNorm -> g_hn
    groupnorm_kernel<<<dim3(NGRP, BATCH), 256>>>(x, gamma, beta);

    // 2) q,k,v = W @ hn + b   (NN layout: A k-contig, B n-contig)
    dim3 gQKV(NPIX / 64, CH / 64, BATCH);
    gemm_kernel<true, true, 1><<<gQKV, 256>>>(
        Wq, 0, nullptr, 1, nullptr, 2, NPIX, CH,
        CH, 1, NPIX, 1, 0, CN, CN, bq, nullptr, 0, 0.f);
    gemm_kernel<true, true, 1><<<gQKV, 256>>>(
        Wk, 0, nullptr, 1, nullptr, 3, NPIX, CH,
        CH, 1, NPIX, 1, 0, CN, CN, bk, nullptr, 0, 0.f);
    gemm_kernel<true, true, 1><<<gQKV, 256>>>(
        Wv, 0, nullptr, 1, nullptr, 4, NPIX, CH,
        CH, 1, NPIX, 1, 0, CN, CN, bv, nullptr, 0, 0.f);

    // 3) scores = (q^T k) * scale   (TN: A m-contig, B n-contig)
    dim3 gS(NPIX / 64, NPIX / 64, BATCH);
    gemm_kernel<false, true, 2><<<gS, 256>>>(
        nullptr, 2, nullptr, 3, nullptr, 5, NPIX, CH,
        1, NPIX, NPIX, 1, CN, CN, NN, nullptr, nullptr, 0, scale);

    // 4) softmax rows of g_s (in place)
    softmax_kernel<<<BATCH * NPIX, 256>>>();

    // 5) o[c,i] = sum_j v[c,j] attn[i,j]   (NT: A k-contig, B k-contig)
    dim3 gAV(NPIX / 64, CH / 64, BATCH);
    gemm_kernel<true, false, 0><<<gAV, 256>>>(
        nullptr, 4, nullptr, 5, nullptr, 6, NPIX, NPIX,
        NPIX, 1, 1, NPIX, CN, NN, CN, nullptr, nullptr, 0, 0.f);

    // 6) out = x + Wo @ o + bo  (NN + bias + residual, into d_out)
    gemm_kernel<true, true, 3><<<gQKV, 256>>>(
        Wo, 0, nullptr, 6, out, 0, NPIX, CH,
        CH, 1, NPIX, 1, 0, CN, CN, bo, x, CN, 0.f);

    (void)in_sizes; (void)n_in; (void)out_size;
}

// round 5
// speedup vs baseline: 2.5214x; 2.5214x over previous
#include <cuda_runtime.h>
#include <cuda_bf16.h>
#include <cstdint>
#include <cmath>

#define BATCH 2
#define CH    512
#define NPIX  4096
#define NFOLD (BATCH * NPIX)     // 8192
#define EPS   1e-6f

using bf16 = __nv_bfloat16;

// ------------------------- scratch (device globals) -------------------------
static __device__ float2 g_stats[BATCH * 32];
static __device__ bf16 g_w_hi[4 * CH * CH];
static __device__ bf16 g_w_lo[4 * CH * CH];
static __device__ bf16 g_hnT_hi[(size_t)NFOLD * CH];
static __device__ bf16 g_hnT_lo[(size_t)NFOLD * CH];
static __device__ bf16 g_qT_hi[(size_t)NFOLD * CH];
static __device__ bf16 g_qT_lo[(size_t)NFOLD * CH];
static __device__ bf16 g_kT_hi[(size_t)NFOLD * CH];
static __device__ bf16 g_kT_lo[(size_t)NFOLD * CH];
static __device__ bf16 g_v_hi[(size_t)BATCH * CH * NPIX];
static __device__ bf16 g_v_lo[(size_t)BATCH * CH * NPIX];
static __device__ float g_s[(size_t)BATCH * NPIX * NPIX];        // 134 MB
static __device__ bf16 g_at_hi[(size_t)BATCH * NPIX * NPIX];     // 67 MB
static __device__ bf16 g_at_lo[(size_t)BATCH * NPIX * NPIX];     // 67 MB
static __device__ bf16 g_oT_hi[(size_t)NFOLD * CH];
static __device__ bf16 g_oT_lo[(size_t)NFOLD * CH];

// ------------------------- small helpers -------------------------
__device__ __forceinline__ uint32_t smem_u32(const void* p) {
    uint32_t a;
    asm("{ .reg .u64 t; cvta.to.shared.u64 t, %1; cvt.u32.u64 %0, t; }"
        : "=r"(a) : "l"(p));
    return a;
}

__device__ __forceinline__ void split2(float v, bf16& hi, bf16& lo) {
    hi = __float2bfloat16(v);
    lo = __float2bfloat16(v - __bfloat162float(hi));
}

__device__ __forceinline__ void cp16(uint32_t s, const void* g) {
    asm volatile("cp.async.cg.shared.global [%0], [%1], 16;" :: "r"(s), "l"(g));
}

#define CP_COMMIT() asm volatile("cp.async.commit_group;" ::: "memory")

#define LDSM4(R, addr) \
    asm volatile("ldmatrix.sync.aligned.m8n8.x4.shared.b16 {%0,%1,%2,%3}, [%4];" \
        : "=r"((R)[0]), "=r"((R)[1]), "=r"((R)[2]), "=r"((R)[3]) : "r"(addr))

#define LDSM2(R, addr) \
    asm volatile("ldmatrix.sync.aligned.m8n8.x2.shared.b16 {%0,%1}, [%2];" \
        : "=r"((R)[0]), "=r"((R)[1]) : "r"(addr))

#define MMA16816(D, A, B) \
    asm volatile("mma.sync.aligned.m16n8k16.row.col.f32.bf16.bf16.f32 " \
        "{%0,%1,%2,%3}, {%4,%5,%6,%7}, {%8,%9}, {%0,%1,%2,%3};" \
        : "+f"((D)[0]), "+f"((D)[1]), "+f"((D)[2]), "+f"((D)[3]) \
        : "r"((A)[0]), "r"((A)[1]), "r"((A)[2]), "r"((A)[3]), \
          "r"((B)[0]), "r"((B)[1]))

// ------------------------- W fp32 -> bf16 hi/lo -------------------------
__global__ void __launch_bounds__(256) convert_w_kernel(
    const float* __restrict__ src, bf16* __restrict__ hi, bf16* __restrict__ lo)
{
    int i = blockIdx.x * 256 + threadIdx.x;     // float4 index, exact grid
    float4 v = ((const float4*)src)[i];
    int e = i * 4;
    bf16 h, l;
    split2(v.x, h, l); hi[e + 0] = h; lo[e + 0] = l;
    split2(v.y, h, l); hi[e + 1] = h; lo[e + 1] = l;
    split2(v.z, h, l); hi[e + 2] = h; lo[e + 2] = l;
    split2(v.w, h, l); hi[e + 3] = h; lo[e + 3] = l;
}

// ------------------------- GroupNorm stats -------------------------
__global__ void __launch_bounds__(256) gn_stats_kernel(const float* __restrict__ x)
{
    const int g = blockIdx.x, b = blockIdx.y;
    const size_t base = ((size_t)b * CH + (size_t)g * 16) * NPIX;
    const float4* x4 = (const float4*)(x + base);
    const int n4 = 16 * NPIX / 4;

    float s = 0.f, ss = 0.f;
    for (int i = threadIdx.x; i < n4; i += 256) {
        float4 v = x4[i];
        s  += v.x + v.y + v.z + v.w;
        ss += v.x * v.x + v.y * v.y + v.z * v.z + v.w * v.w;
    }
    __shared__ float rs[8], rss[8];
    #pragma unroll
    for (int o = 16; o; o >>= 1) {
        s  += __shfl_xor_sync(0xffffffffu, s, o);
        ss += __shfl_xor_sync(0xffffffffu, ss, o);
    }
    const int lane = threadIdx.x & 31, wid = threadIdx.x >> 5;
    if (lane == 0) { rs[wid] = s; rss[wid] = ss; }
    __syncthreads();
    if (threadIdx.x == 0) {
        float ts = 0.f, tss = 0.f;
        #pragma unroll
        for (int i = 0; i < 8; i++) { ts += rs[i]; tss += rss[i]; }
        const float inv_n = 1.0f / (16 * NPIX);
        float mean = ts * inv_n;
        float var = tss * inv_n - mean * mean;
        g_stats[b * 32 + g] = make_float2(mean, rsqrtf(var + EPS));
    }
}

// ---------- transpose + normalize + hi/lo convert:  x[b,c,n] -> hnT[b*N+n, c] ----------
__global__ void __launch_bounds__(256) tnc_kernel(
    const float* __restrict__ x, const float* __restrict__ gamma,
    const float* __restrict__ beta)
{
    __shared__ float tile[32][33];
    const int b = blockIdx.z;
    const int n0 = blockIdx.x * 32, c0 = blockIdx.y * 32;
    const int tx = threadIdx.x & 31, ty = threadIdx.x >> 5;   // 32 x 8

    #pragma unroll
    for (int j = 0; j < 4; j++) {
        int c = c0 + ty + j * 8;
        float2 st = g_stats[b * 32 + (c >> 4)];
        float gm = gamma[c] * st.y;
        float bt = beta[c] - st.x * gm;
        float v = x[((size_t)(b * CH + c)) * NPIX + n0 + tx];
        tile[ty + j * 8][tx] = v * gm + bt;
    }
    __syncthreads();
    #pragma unroll
    for (int j = 0; j < 4; j++) {
        int n = n0 + ty + j * 8;
        float v = tile[tx][ty + j * 8];
        bf16 h, l; split2(v, h, l);
        size_t a = ((size_t)(b * NPIX + n)) * CH + c0 + tx;
        g_hnT_hi[a] = h; g_hnT_lo[a] = l;
    }
}

// ------------------------- mma.sync GEMM -------------------------
// D[m,n] = sum_k A[m,k]*B[n,k], A/B K-major bf16 hi+lo (3-term split), fp32 acc.
// CTA tile: 128(M) x 256(N), K-chunk 32, 3-stage cp.async pipeline.
// 512 threads = 16 warps in 4x4, warp tile 32x64.
#define ROWB     80
#define OFF_AH   0
#define OFF_AL   10240
#define OFF_BH   20480
#define OFF_BL   40960
#define STAGE    61440
#define SMEM_GEMM (3 * STAGE)    // 184320; epilogue reuses 66048 of it

enum { EPI_QKT = 0, EPI_V = 1, EPI_S = 2, EPI_AV = 3, EPI_P = 4 };

__device__ __forceinline__ void load_stage(
    uint32_t so,
    const bf16* __restrict__ Ah, const bf16* __restrict__ Al,
    const bf16* __restrict__ Bh, const bf16* __restrict__ Bl,
    int K, int k0, int tid)
{
    const int r = tid >> 2, c = tid & 3;      // r 0..127, c 0..3 (16B chunks)
    const int go  = r * K + k0 + c * 8;
    const int go2 = go + 128 * K;
    const uint32_t s1 = so + (uint32_t)r * ROWB + c * 16;
    const uint32_t s2 = so + (uint32_t)(r + 128) * ROWB + c * 16;
    cp16(s1 + OFF_AH, Ah + go);
    cp16(s1 + OFF_AL, Al + go);
    cp16(s1 + OFF_BH, Bh + go);
    cp16(s2 + OFF_BH, Bh + go2);
    cp16(s1 + OFF_BL, Bl + go);
    cp16(s2 + OFF_BL, Bl + go2);
}

__device__ __forceinline__ void compute_chunk(
    uint32_t so, int wm, int wn, int lane, float acc[2][8][4])
{
    const uint32_t a_base = so + OFF_AH
        + (uint32_t)(wm + (lane & 15)) * ROWB + ((lane >> 4) << 4);
    const uint32_t b_base = so + OFF_BH
        + (uint32_t)(wn + (lane & 7)) * ROWB + (((lane >> 3) & 1) << 4);
    #pragma unroll
    for (int ks = 0; ks < 2; ks++) {
        uint32_t ah[2][4], al[2][4];
        LDSM4(ah[0], a_base + ks * 32);
        LDSM4(ah[1], a_base + ks * 32 + 16 * ROWB);
        LDSM4(al[0], a_base + ks * 32 + (OFF_AL - OFF_AH));
        LDSM4(al[1], a_base + ks * 32 + (OFF_AL - OFF_AH) + 16 * ROWB);
        #pragma unroll
        for (int nt = 0; nt < 8; nt++) {
            uint32_t bh[2], bl[2];
            LDSM2(bh, b_base + ks * 32 + nt * 8 * ROWB);
            LDSM2(bl, b_base + ks * 32 + nt * 8 * ROWB + (OFF_BL - OFF_BH));
            #pragma unroll
            for (int mt = 0; mt < 2; mt++) {
                MMA16816(acc[mt][nt], ah[mt], bh);
                MMA16816(acc[mt][nt], ah[mt], bl);
                MMA16816(acc[mt][nt], al[mt], bh);
            }
        }
    }
}

template<int EPI>
__global__ void __launch_bounds__(512) gemm_mma(
    const bf16* __restrict__ Ahi, const bf16* __restrict__ Alo,
    const bf16* __restrict__ Bhi, const bf16* __restrict__ Blo,
    int K, size_t Az, size_t Bz,
    bf16* __restrict__ Ohi, bf16* __restrict__ Olo,
    float* __restrict__ Ofp, const float* __restrict__ bias,
    const float* __restrict__ resid, float scale)
{
    extern __shared__ __align__(16) uint8_t gsm[];
    const uint32_t sbase = smem_u32(gsm);
    const int tid = threadIdx.x, lane = tid & 31, wid = tid >> 5;
    const int wm = (wid >> 2) * 32, wn = (wid & 3) * 64;
    const int bz = blockIdx.z;
    const int m0 = blockIdx.y * 128, n0 = blockIdx.x * 256;

    const bf16* Ah = Ahi + (size_t)bz * Az + (size_t)m0 * K;
    const bf16* Al = Alo + (size_t)bz * Az + (size_t)m0 * K;
    const bf16* Bh = Bhi + (size_t)bz * Bz + (size_t)n0 * K;
    const bf16* Bl = Blo + (size_t)bz * Bz + (size_t)n0 * K;

    const int NT = K / 32;
    float acc[2][8][4] = {};

    load_stage(sbase + 0 * STAGE, Ah, Al, Bh, Bl, K, 0, tid);
    CP_COMMIT();
    load_stage(sbase + 1 * STAGE, Ah, Al, Bh, Bl, K, 32, tid);
    CP_COMMIT();

    int buf = 0;
    for (int t = 0; t < NT; t++) {
        if (t + 2 < NT) {
            int nb = t + 2;
            load_stage(sbase + (uint32_t)(nb % 3) * STAGE, Ah, Al, Bh, Bl, K, nb * 32, tid);
            CP_COMMIT();
            asm volatile("cp.async.wait_group 2;" ::: "memory");
        } else if (t + 1 < NT) {
            asm volatile("cp.async.wait_group 1;" ::: "memory");
        } else {
            asm volatile("cp.async.wait_group 0;" ::: "memory");
        }
        __syncthreads();
        compute_chunk(sbase + (uint32_t)buf * STAGE, wm, wn, lane, acc);
        __syncthreads();
        buf++; if (buf == 3) buf = 0;
    }

    // -------- epilogue: two 128-col halves staged through smem (coalesced I/O) --------
    float* Sf = (float*)gsm;
    const int grp = lane >> 2, tg = lane & 3;
    const int rr = tid >> 5;        // 0..15
    const int cc = tid & 31;        // 0..31

    #pragma unroll 1
    for (int h = 0; h < 2; h++) {
        __syncthreads();
        if (((wid & 3) >> 1) == h) {
            const int nbase = (wid & 1) * 64;
            #pragma unroll
            for (int mt = 0; mt < 2; mt++) {
                #pragma unroll
                for (int nt = 0; nt < 8; nt++) {
                    int m = wm + mt * 16 + grp;
                    int n = nbase + nt * 8 + tg * 2;
                    Sf[m * 129 + n]           = acc[mt][nt][0];
                    Sf[m * 129 + n + 1]       = acc[mt][nt][1];
                    Sf[(m + 8) * 129 + n]     = acc[mt][nt][2];
                    Sf[(m + 8) * 129 + n + 1] = acc[mt][nt][3];
                }
            }
        }
        __syncthreads();
        const int nglob = n0 + h * 128;

        #pragma unroll 1
        for (int it = 0; it < 8; it++) {
            const int r = rr + it * 16;
            if (EPI == EPI_S) {
                const float* s = &Sf[r * 129 + cc * 4];
                float4 o = make_float4(s[0] * scale, s[1] * scale,
                                       s[2] * scale, s[3] * scale);
                *(float4*)&Ofp[((size_t)bz * NPIX + m0 + r) * NPIX + nglob + cc * 4] = o;
            } else if (EPI == EPI_P) {
                const float bv = bias[m0 + r];
                size_t a = ((size_t)((nglob >> 12) * CH + m0 + r)) * NPIX
                         + (nglob & (NPIX - 1)) + cc * 4;
                float4 rd = *(const float4*)&resid[a];
                const float* s = &Sf[r * 129 + cc * 4];
                float4 o = make_float4(s[0] + bv + rd.x, s[1] + bv + rd.y,
                                       s[2] + bv + rd.z, s[3] + bv + rd.w);
                *(float4*)&Ofp[a] = o;
            } else if (EPI == EPI_V) {
                const float bv = bias[m0 + r];
                size_t a = ((size_t)((nglob >> 12) * CH + m0 + r)) * NPIX
                         + (nglob & (NPIX - 1)) + cc * 4;
                const float* s = &Sf[r * 129 + cc * 4];
                bf16 h0, l0, h1, l1, h2, l2, h3, l3;
                split2(s[0] + bv, h0, l0); split2(s[1] + bv, h1, l1);
                split2(s[2] + bv, h2, l2); split2(s[3] + bv, h3, l3);
                *(__nv_bfloat162*)&Ohi[a]     = __halves2bfloat162(h0, h1);
                *(__nv_bfloat162*)&Ohi[a + 2] = __halves2bfloat162(h2, h3);
                *(__nv_bfloat162*)&Olo[a]     = __halves2bfloat162(l0, l1);
                *(__nv_bfloat162*)&Olo[a + 2] = __halves2bfloat162(l2, l3);
            } else {   // EPI_QKT / EPI_AV : transposed output O[n*CH + m]
                size_t ng = (size_t)nglob + r;
                if (EPI == EPI_AV) ng += (size_t)bz * NPIX;
                size_t a = ng * CH + m0 + cc * 4;
                float v0 = Sf[(cc * 4 + 0) * 129 + r];
                float v1 = Sf[(cc * 4 + 1) * 129 + r];
                float v2 = Sf[(cc * 4 + 2) * 129 + r];
                float v3 = Sf[(cc * 4 + 3) * 129 + r];
                if (EPI == EPI_QKT) {
                    v0 += bias[m0 + cc * 4 + 0];
                    v1 += bias[m0 + cc * 4 + 1];
                    v2 += bias[m0 + cc * 4 + 2];
                    v3 += bias[m0 + cc * 4 + 3];
                }
                bf16 h0, l0, h1, l1, h2, l2, h3, l3;
                split2(v0, h0, l0); split2(v1, h1, l1);
                split2(v2, h2, l2); split2(v3, h3, l3);
                *(__nv_bfloat162*)&Ohi[a]     = __halves2bfloat162(h0, h1);
                *(__nv_bfloat162*)&Ohi[a + 2] = __halves2bfloat162(h2, h3);
                *(__nv_bfloat162*)&Olo[a]     = __halves2bfloat162(l0, l1);
                *(__nv_bfloat162*)&Olo[a + 2] = __halves2bfloat162(l2, l3);
            }
        }
    }
}

// -------------- softmax rows of g_s -> attn bf16 hi/lo --------------
__global__ void __launch_bounds__(256) softmax_kernel()
{
    const size_t row = blockIdx.x;       // 0 .. NFOLD-1
    const float4* p = (const float4*)(g_s + row * NPIX);
    __nv_bfloat162* oh = (__nv_bfloat162*)(g_at_hi + row * NPIX);
    __nv_bfloat162* ol = (__nv_bfloat162*)(g_at_lo + row * NPIX);
    const int t = threadIdx.x;
    const int lane = t & 31, wid = t >> 5;

    float4 v[4];
    float mx = -1e30f;
    #pragma unroll
    for (int i = 0; i < 4; i++) {
        v[i] = p[t + 256 * i];
        mx = fmaxf(mx, fmaxf(fmaxf(v[i].x, v[i].y), fmaxf(v[i].z, v[i].w)));
    }
    __shared__ float red[8];
    __shared__ float s_mx, s_sum;
    #pragma unroll
    for (int o = 16; o; o >>= 1) mx = fmaxf(mx, __shfl_xor_sync(0xffffffffu, mx, o));
    if (lane == 0) red[wid] = mx;
    __syncthreads();
    if (t == 0) {
        float m = red[0];
        #pragma unroll
        for (int i = 1; i < 8; i++) m = fmaxf(m, red[i]);
        s_mx = m;
    }
    __syncthreads();
    mx = s_mx;

    float sum = 0.f;
    #pragma unroll
    for (int i = 0; i < 4; i++) {
        v[i].x = __expf(v[i].x - mx);
        v[i].y = __expf(v[i].y - mx);
        v[i].z = __expf(v[i].z - mx);
        v[i].w = __expf(v[i].w - mx);
        sum += v[i].x + v[i].y + v[i].z + v[i].w;
    }
    #pragma unroll
    for (int o = 16; o; o >>= 1) sum += __shfl_xor_sync(0xffffffffu, sum, o);
    if (lane == 0) red[wid] = sum;
    __syncthreads();
    if (t == 0) {
        float s = 0.f;
        #pragma unroll
        for (int i = 0; i < 8; i++) s += red[i];
        s_sum = s;
    }
    __syncthreads();
    const float inv = 1.0f / s_sum;

    #pragma unroll
    for (int i = 0; i < 4; i++) {
        float e0 = v[i].x * inv, e1 = v[i].y * inv, e2 = v[i].z * inv, e3 = v[i].w * inv;
        bf16 h0, l0, h1, l1, h2, l2, h3, l3;
        split2(e0, h0, l0); split2(e1, h1, l1);
        split2(e2, h2, l2); split2(e3, h3, l3);
        int bi = (t + 256 * i) * 2;
        oh[bi + 0] = __halves2bfloat162(h0, h1);
        oh[bi + 1] = __halves2bfloat162(h2, h3);
        ol[bi + 0] = __halves2bfloat162(l0, l1);
        ol[bi + 1] = __halves2bfloat162(l2, l3);
    }
}

// ------------------------- launcher -------------------------
extern "C" void kernel_launch(void* const* d_in, const int* in_sizes, int n_in,
                              void* d_out, int out_size)
{
    const float* x     = (const float*)d_in[0];
    const float* gamma = (const float*)d_in[1];
    const float* beta  = (const float*)d_in[2];
    const float* Wq    = (const float*)d_in[3];
    const float* bq    = (const float*)d_in[4];
    const float* Wk    = (const float*)d_in[5];
    const float* bk    = (const float*)d_in[6];
    const float* Wv    = (const float*)d_in[7];
    const float* bv    = (const float*)d_in[8];
    const float* Wo    = (const float*)d_in[9];
    const float* bo    = (const float*)d_in[10];
    float* out = (float*)d_out;

    void* p;
    bf16 *w_hi, *w_lo, *hnT_hi, *hnT_lo, *qT_hi, *qT_lo, *kT_hi, *kT_lo;
    bf16 *v_hi, *v_lo, *at_hi, *at_lo, *oT_hi, *oT_lo;
    float* s_ptr;
    cudaGetSymbolAddress(&p, g_w_hi);   w_hi   = (bf16*)p;
    cudaGetSymbolAddress(&p, g_w_lo);   w_lo   = (bf16*)p;
    cudaGetSymbolAddress(&p, g_hnT_hi); hnT_hi = (bf16*)p;
    cudaGetSymbolAddress(&p, g_hnT_lo); hnT_lo = (bf16*)p;
    cudaGetSymbolAddress(&p, g_qT_hi);  qT_hi  = (bf16*)p;
    cudaGetSymbolAddress(&p, g_qT_lo);  qT_lo  = (bf16*)p;
    cudaGetSymbolAddress(&p, g_kT_hi);  kT_hi  = (bf16*)p;
    cudaGetSymbolAddress(&p, g_kT_lo);  kT_lo  = (bf16*)p;
    cudaGetSymbolAddress(&p, g_v_hi);   v_hi   = (bf16*)p;
    cudaGetSymbolAddress(&p, g_v_lo);   v_lo   = (bf16*)p;
    cudaGetSymbolAddress(&p, g_at_hi);  at_hi  = (bf16*)p;
    cudaGetSymbolAddress(&p, g_at_lo);  at_lo  = (bf16*)p;
    cudaGetSymbolAddress(&p, g_oT_hi);  oT_hi  = (bf16*)p;
    cudaGetSymbolAddress(&p, g_oT_lo);  oT_lo  = (bf16*)p;
    cudaGetSymbolAddress(&p, g_s);      s_ptr  = (float*)p;

    cudaFuncSetAttribute(gemm_mma<EPI_QKT>, cudaFuncAttributeMaxDynamicSharedMemorySize, SMEM_GEMM);
    cudaFuncSetAttribute(gemm_mma<EPI_V>,   cudaFuncAttributeMaxDynamicSharedMemorySize, SMEM_GEMM);
    cudaFuncSetAttribute(gemm_mma<EPI_S>,   cudaFuncAttributeMaxDynamicSharedMemorySize, SMEM_GEMM);
    cudaFuncSetAttribute(gemm_mma<EPI_AV>,  cudaFuncAttributeMaxDynamicSharedMemorySize, SMEM_GEMM);
    cudaFuncSetAttribute(gemm_mma<EPI_P>,   cudaFuncAttributeMaxDynamicSharedMemorySize, SMEM_GEMM);

    const float scale = 1.0f / sqrtf((float)CH);
    const size_t WN = (size_t)CH * CH;

    convert_w_kernel<<<WN / 4 / 256, 256>>>(Wq, w_hi + 0 * WN, w_lo + 0 * WN);
    convert_w_kernel<<<WN / 4 / 256, 256>>>(Wk, w_hi + 1 * WN, w_lo + 1 * WN);
    convert_w_kernel<<<WN / 4 / 256, 256>>>(Wv, w_hi + 2 * WN, w_lo + 2 * WN);
    convert_w_kernel<<<WN / 4 / 256, 256>>>(Wo, w_hi + 3 * WN, w_lo + 3 * WN);

    gn_stats_kernel<<<dim3(32, BATCH), 256>>>(x);
    tnc_kernel<<<dim3(NPIX / 32, CH / 32, BATCH), 256>>>(x, gamma, beta);

    // qkv: D[o, nf] over K=CH; B = hnT [NFOLD, CH]
    dim3 gQKV(NFOLD / 256, CH / 128, 1);
    gemm_mma<EPI_QKT><<<gQKV, 512, SMEM_GEMM>>>(
        w_hi + 0 * WN, w_lo + 0 * WN, hnT_hi, hnT_lo, CH, 0, 0,
        qT_hi, qT_lo, nullptr, bq, nullptr, 0.f);
    gemm_mma<EPI_QKT><<<gQKV, 512, SMEM_GEMM>>>(
        w_hi + 1 * WN, w_lo + 1 * WN, hnT_hi, hnT_lo, CH, 0, 0,
        kT_hi, kT_lo, nullptr, bk, nullptr, 0.f);
    gemm_mma<EPI_V><<<gQKV, 512, SMEM_GEMM>>>(
        w_hi + 2 * WN, w_lo + 2 * WN, hnT_hi, hnT_lo, CH, 0, 0,
        v_hi, v_lo, nullptr, bv, nullptr, 0.f);

    // scores
    dim3 gS(NPIX / 256, NPIX / 128, BATCH);
    gemm_mma<EPI_S><<<gS, 512, SMEM_GEMM>>>(
        qT_hi, qT_lo, kT_hi, kT_lo, CH,
        (size_t)NPIX * CH, (size_t)NPIX * CH,
        nullptr, nullptr, s_ptr, nullptr, nullptr, scale);

    softmax_kernel<<<NFOLD, 256>>>();

    // AV: o[c,i] = sum_j v[c,j]*attn[i,j] -> oT
    dim3 gAV(NPIX / 256, CH / 128, BATCH);
    gemm_mma<EPI_AV><<<gAV, 512, SMEM_GEMM>>>(
        v_hi, v_lo, at_hi, at_lo, NPIX,
        (size_t)CH * NPIX, (size_t)NPIX * NPIX,
        oT_hi, oT_lo, nullptr, nullptr, nullptr, 0.f);

    // proj + bias + residual -> out
    dim3 gP(NFOLD / 256, CH / 128, 1);
    gemm_mma<EPI_P><<<gP, 512, SMEM_GEMM>>>(
        w_hi + 3 * WN, w_lo + 3 * WN, oT_hi, oT_lo, CH, 0, 0,
        nullptr, nullptr, out, bo, x, 0.f);

    (void)in_sizes; (void)n_in; (void)out_size;
}

// round 6
// speedup vs baseline: 3.6393x; 1.4434x over previous
#include <cuda_runtime.h>
#include <cuda_fp16.h>
#include <cstdint>
#include <cmath>

#define BATCH 2
#define CH    512
#define NPIX  4096
#define NFOLD (BATCH * NPIX)     // 8192
#define EPS   1e-6f

// ------------------------- scratch (device globals) -------------------------
static __device__ float2 g_stats[BATCH * 32];
static __device__ __half g_w_hi[4 * CH * CH];
static __device__ __half g_w_lo[4 * CH * CH];
static __device__ __half g_hnT[(size_t)NFOLD * CH];
static __device__ __half g_qT_hi[(size_t)NFOLD * CH];
static __device__ __half g_qT_lo[(size_t)NFOLD * CH];
static __device__ __half g_kT[(size_t)NFOLD * CH];
static __device__ __half g_v_hi[(size_t)BATCH * CH * NPIX];
static __device__ __half g_v_lo[(size_t)BATCH * CH * NPIX];
static __device__ float  g_s[(size_t)BATCH * NPIX * NPIX];     // 134 MB
static __device__ __half g_at[(size_t)BATCH * NPIX * NPIX];    // 67 MB
static __device__ __half g_oT[(size_t)NFOLD * CH];

// ------------------------- small helpers -------------------------
__device__ __forceinline__ uint32_t smem_u32(const void* p) {
    uint32_t a;
    asm("{ .reg .u64 t; cvta.to.shared.u64 t, %1; cvt.u32.u64 %0, t; }"
        : "=r"(a) : "l"(p));
    return a;
}

__device__ __forceinline__ void split2h(float v, __half& hi, __half& lo) {
    hi = __float2half_rn(v);
    lo = __float2half_rn(v - __half2float(hi));
}

__device__ __forceinline__ void cp16(uint32_t s, const void* g) {
    asm volatile("cp.async.cg.shared.global [%0], [%1], 16;" :: "r"(s), "l"(g));
}

#define CP_COMMIT() asm volatile("cp.async.commit_group;" ::: "memory")

#define LDSM4(R, addr) \
    asm volatile("ldmatrix.sync.aligned.m8n8.x4.shared.b16 {%0,%1,%2,%3}, [%4];" \
        : "=r"((R)[0]), "=r"((R)[1]), "=r"((R)[2]), "=r"((R)[3]) : "r"(addr))

#define MMA16816(D, A, B) \
    asm volatile("mma.sync.aligned.m16n8k16.row.col.f32.f16.f16.f32 " \
        "{%0,%1,%2,%3}, {%4,%5,%6,%7}, {%8,%9}, {%0,%1,%2,%3};" \
        : "+f"((D)[0]), "+f"((D)[1]), "+f"((D)[2]), "+f"((D)[3]) \
        : "r"((A)[0]), "r"((A)[1]), "r"((A)[2]), "r"((A)[3]), \
          "r"((B)[0]), "r"((B)[1]))

// ------------------------- all W fp32 -> fp16 hi/lo (one launch) -------------------------
__global__ void __launch_bounds__(256) convert_w4_kernel(
    const float* __restrict__ w0, const float* __restrict__ w1,
    const float* __restrict__ w2, const float* __restrict__ w3)
{
    const float* src = (blockIdx.y == 0) ? w0 : (blockIdx.y == 1) ? w1
                     : (blockIdx.y == 2) ? w2 : w3;
    int i = blockIdx.x * 256 + threadIdx.x;     // float4 index within one W
    float4 v = ((const float4*)src)[i];
    size_t e = (size_t)blockIdx.y * CH * CH + (size_t)i * 4;
    __half h, l;
    split2h(v.x, h, l); g_w_hi[e + 0] = h; g_w_lo[e + 0] = l;
    split2h(v.y, h, l); g_w_hi[e + 1] = h; g_w_lo[e + 1] = l;
    split2h(v.z, h, l); g_w_hi[e + 2] = h; g_w_lo[e + 2] = l;
    split2h(v.w, h, l); g_w_hi[e + 3] = h; g_w_lo[e + 3] = l;
}

// ------------------------- GroupNorm stats -------------------------
__global__ void __launch_bounds__(256) gn_stats_kernel(const float* __restrict__ x)
{
    const int g = blockIdx.x, b = blockIdx.y;
    const size_t base = ((size_t)b * CH + (size_t)g * 16) * NPIX;
    const float4* x4 = (const float4*)(x + base);
    const int n4 = 16 * NPIX / 4;

    float s = 0.f, ss = 0.f;
    for (int i = threadIdx.x; i < n4; i += 256) {
        float4 v = x4[i];
        s  += v.x + v.y + v.z + v.w;
        ss += v.x * v.x + v.y * v.y + v.z * v.z + v.w * v.w;
    }
    __shared__ float rs[8], rss[8];
    #pragma unroll
    for (int o = 16; o; o >>= 1) {
        s  += __shfl_xor_sync(0xffffffffu, s, o);
        ss += __shfl_xor_sync(0xffffffffu, ss, o);
    }
    const int lane = threadIdx.x & 31, wid = threadIdx.x >> 5;
    if (lane == 0) { rs[wid] = s; rss[wid] = ss; }
    __syncthreads();
    if (threadIdx.x == 0) {
        float ts = 0.f, tss = 0.f;
        #pragma unroll
        for (int i = 0; i < 8; i++) { ts += rs[i]; tss += rss[i]; }
        const float inv_n = 1.0f / (16 * NPIX);
        float mean = ts * inv_n;
        float var = tss * inv_n - mean * mean;
        g_stats[b * 32 + g] = make_float2(mean, rsqrtf(var + EPS));
    }
}

// ---------- transpose + normalize + fp16 convert:  x[b,c,n] -> hnT[b*N+n, c] ----------
__global__ void __launch_bounds__(256) tnc_kernel(
    const float* __restrict__ x, const float* __restrict__ gamma,
    const float* __restrict__ beta)
{
    __shared__ float tile[32][33];
    const int b = blockIdx.z;
    const int n0 = blockIdx.x * 32, c0 = blockIdx.y * 32;
    const int tx = threadIdx.x & 31, ty = threadIdx.x >> 5;   // 32 x 8

    #pragma unroll
    for (int j = 0; j < 4; j++) {
        int c = c0 + ty + j * 8;
        float2 st = g_stats[b * 32 + (c >> 4)];
        float gm = gamma[c] * st.y;
        float bt = beta[c] - st.x * gm;
        float v = x[((size_t)(b * CH + c)) * NPIX + n0 + tx];
        tile[ty + j * 8][tx] = v * gm + bt;
    }
    __syncthreads();
    #pragma unroll
    for (int j = 0; j < 4; j++) {
        int n = n0 + ty + j * 8;
        float v = tile[tx][ty + j * 8];
        size_t a = ((size_t)(b * NPIX + n)) * CH + c0 + tx;
        g_hnT[a] = __float2half_rn(v);
    }
}

// ------------------------- mma.sync GEMM (fp16 2-term) -------------------------
// D[m,n] = sum_k (Ah+Al)[m,k]*B[n,k], all K-major fp16, fp32 acc.
// CTA: 128(M) x 256(N), K-chunk 32, 4-stage cp.async pipeline, 512 thr (16 warps 4x4).
#define ROWB     80
#define OFF_AL   10240
#define OFF_B    20480
#define STAGE    40960
#define SMEM_GEMM (4 * STAGE)    // 163840; epilogue reuses 66048

enum { EPI_Q = 0, EPI_K = 1, EPI_V = 2, EPI_S = 3, EPI_AV = 4, EPI_P = 5 };

__device__ __forceinline__ void load_stage(
    uint32_t so,
    const __half* __restrict__ Ah, const __half* __restrict__ Al,
    const __half* __restrict__ B, int K, int k0, int tid)
{
    const int r = tid >> 2, c = tid & 3;       // r 0..127, c = 16B chunk
    const int go = r * K + k0 + c * 8;
    const uint32_t sA = so + (uint32_t)r * ROWB + c * 16;
    cp16(sA, Ah + go);
    cp16(sA + OFF_AL, Al + go);
    const uint32_t sB = so + OFF_B + (uint32_t)r * ROWB + c * 16;
    cp16(sB, B + go);
    cp16(sB + 128 * ROWB, B + go + 128 * K);
}

__device__ __forceinline__ void compute_chunk(
    uint32_t so, int wm, int wn, int lane, float acc[2][8][4])
{
    const uint32_t a_base = so + (uint32_t)(wm + (lane & 15)) * ROWB + ((lane >> 4) << 4);
    const uint32_t b_base = so + OFF_B
        + (uint32_t)(wn + ((lane >> 4) << 3) + (lane & 7)) * ROWB
        + (((lane >> 3) & 1) << 4);
    #pragma unroll
    for (int ks = 0; ks < 2; ks++) {
        uint32_t ah[2][4], al[2][4];
        LDSM4(ah[0], a_base + ks * 32);
        LDSM4(ah[1], a_base + ks * 32 + 16 * ROWB);
        LDSM4(al[0], a_base + ks * 32 + OFF_AL);
        LDSM4(al[1], a_base + ks * 32 + OFF_AL + 16 * ROWB);
        #pragma unroll
        for (int np = 0; np < 4; np++) {
            uint32_t bb[4];                     // two n8 fragments
            LDSM4(bb, b_base + ks * 32 + np * 16 * ROWB);
            #pragma unroll
            for (int mt = 0; mt < 2; mt++) {
                MMA16816(acc[mt][np * 2 + 0], ah[mt], bb);
                MMA16816(acc[mt][np * 2 + 0], al[mt], bb);
                MMA16816(acc[mt][np * 2 + 1], ah[mt], bb + 2);
                MMA16816(acc[mt][np * 2 + 1], al[mt], bb + 2);
            }
        }
    }
}

template<int EPI>
__global__ void __launch_bounds__(512) gemm_mma(
    const __half* __restrict__ Ahi, const __half* __restrict__ Alo,
    const __half* __restrict__ B,
    int K, size_t Az, size_t Bz,
    __half* __restrict__ Oh, __half* __restrict__ Ol,
    float* __restrict__ Ofp, const float* __restrict__ bias,
    const float* __restrict__ resid, float scale)
{
    extern __shared__ __align__(16) uint8_t gsm[];
    const uint32_t sbase = smem_u32(gsm);
    const int tid = threadIdx.x, lane = tid & 31, wid = tid >> 5;
    const int wm = (wid >> 2) * 32, wn = (wid & 3) * 64;
    const int bz = blockIdx.z;
    const int m0 = blockIdx.y * 128, n0 = blockIdx.x * 256;

    const __half* Ah = Ahi + (size_t)bz * Az + (size_t)m0 * K;
    const __half* Al = Alo + (size_t)bz * Az + (size_t)m0 * K;
    const __half* Bp = B   + (size_t)bz * Bz + (size_t)n0 * K;

    const int NT = K / 32;
    float acc[2][8][4] = {};

    load_stage(sbase + 0 * STAGE, Ah, Al, Bp, K, 0, tid);  CP_COMMIT();
    load_stage(sbase + 1 * STAGE, Ah, Al, Bp, K, 32, tid); CP_COMMIT();
    load_stage(sbase + 2 * STAGE, Ah, Al, Bp, K, 64, tid); CP_COMMIT();

    for (int t = 0; t < NT; t++) {
        asm volatile("cp.async.wait_group 2;" ::: "memory");
        __syncthreads();
        if (t + 3 < NT) {
            load_stage(sbase + (uint32_t)((t + 3) & 3) * STAGE, Ah, Al, Bp, K,
                       (t + 3) * 32, tid);
            CP_COMMIT();
        }
        compute_chunk(sbase + (uint32_t)(t & 3) * STAGE, wm, wn, lane, acc);
    }
    __syncthreads();

    // -------- epilogue: two 128-col halves staged through smem --------
    float* Sf = (float*)gsm;
    const int grp = lane >> 2, tg = lane & 3;
    const int rr = tid >> 5;        // 0..15
    const int cc = tid & 31;        // 0..31

    #pragma unroll 1
    for (int h = 0; h < 2; h++) {
        __syncthreads();
        if (((wid & 3) >> 1) == h) {
            const int nbase = (wid & 1) * 64;
            #pragma unroll
            for (int mt = 0; mt < 2; mt++) {
                #pragma unroll
                for (int nt = 0; nt < 8; nt++) {
                    int m = wm + mt * 16 + grp;
                    int n = nbase + nt * 8 + tg * 2;
                    Sf[m * 129 + n]           = acc[mt][nt][0];
                    Sf[m * 129 + n + 1]       = acc[mt][nt][1];
                    Sf[(m + 8) * 129 + n]     = acc[mt][nt][2];
                    Sf[(m + 8) * 129 + n + 1] = acc[mt][nt][3];
                }
            }
        }
        __syncthreads();
        const int nglob = n0 + h * 128;

        #pragma unroll 1
        for (int it = 0; it < 8; it++) {
            const int r = rr + it * 16;
            if (EPI == EPI_S) {
                const float* s = &Sf[r * 129 + cc * 4];
                float4 o = make_float4(s[0], s[1], s[2], s[3]);
                *(float4*)&Ofp[((size_t)bz * NPIX + m0 + r) * NPIX + nglob + cc * 4] = o;
            } else if (EPI == EPI_P) {
                const float bv = bias[m0 + r];
                size_t a = ((size_t)((nglob >> 12) * CH + m0 + r)) * NPIX
                         + (nglob & (NPIX - 1)) + cc * 4;
                float4 rd = *(const float4*)&resid[a];
                const float* s = &Sf[r * 129 + cc * 4];
                float4 o = make_float4(s[0] + bv + rd.x, s[1] + bv + rd.y,
                                       s[2] + bv + rd.z, s[3] + bv + rd.w);
                *(float4*)&Ofp[a] = o;
            } else if (EPI == EPI_V) {
                const float bv = bias[m0 + r];
                size_t a = ((size_t)((nglob >> 12) * CH + m0 + r)) * NPIX
                         + (nglob & (NPIX - 1)) + cc * 4;
                const float* s = &Sf[r * 129 + cc * 4];
                __half h0, l0, h1, l1, h2, l2, h3, l3;
                split2h(s[0] + bv, h0, l0); split2h(s[1] + bv, h1, l1);
                split2h(s[2] + bv, h2, l2); split2h(s[3] + bv, h3, l3);
                *(__half2*)&Oh[a]     = __halves2half2(h0, h1);
                *(__half2*)&Oh[a + 2] = __halves2half2(h2, h3);
                *(__half2*)&Ol[a]     = __halves2half2(l0, l1);
                *(__half2*)&Ol[a + 2] = __halves2half2(l2, l3);
            } else {
                // transposed outputs: O[n*CH + m]
                size_t ng = (size_t)nglob + r;
                if (EPI == EPI_AV) ng += (size_t)bz * NPIX;
                size_t a = ng * CH + m0 + cc * 4;
                float v0 = Sf[(cc * 4 + 0) * 129 + r];
                float v1 = Sf[(cc * 4 + 1) * 129 + r];
                float v2 = Sf[(cc * 4 + 2) * 129 + r];
                float v3 = Sf[(cc * 4 + 3) * 129 + r];
                if (EPI == EPI_Q) {
                    v0 = (v0 + bias[m0 + cc * 4 + 0]) * scale;
                    v1 = (v1 + bias[m0 + cc * 4 + 1]) * scale;
                    v2 = (v2 + bias[m0 + cc * 4 + 2]) * scale;
                    v3 = (v3 + bias[m0 + cc * 4 + 3]) * scale;
                    __half h0, l0, h1, l1, h2, l2, h3, l3;
                    split2h(v0, h0, l0); split2h(v1, h1, l1);
                    split2h(v2, h2, l2); split2h(v3, h3, l3);
                    *(__half2*)&Oh[a]     = __halves2half2(h0, h1);
                    *(__half2*)&Oh[a + 2] = __halves2half2(h2, h3);
                    *(__half2*)&Ol[a]     = __halves2half2(l0, l1);
                    *(__half2*)&Ol[a + 2] = __halves2half2(l2, l3);
                } else {   // EPI_K / EPI_AV : single fp16
                    if (EPI == EPI_K) {
                        v0 += bias[m0 + cc * 4 + 0];
                        v1 += bias[m0 + cc * 4 + 1];
                        v2 += bias[m0 + cc * 4 + 2];
                        v3 += bias[m0 + cc * 4 + 3];
                    }
                    *(__half2*)&Oh[a]     = __halves2half2(__float2half_rn(v0),
                                                           __float2half_rn(v1));
                    *(__half2*)&Oh[a + 2] = __halves2half2(__float2half_rn(v2),
                                                           __float2half_rn(v3));
                }
            }
        }
    }
}

// -------------- softmax rows of g_s -> attn fp16 --------------
__global__ void __launch_bounds__(256) softmax_kernel()
{
    const size_t row = blockIdx.x;       // 0 .. NFOLD-1
    const float4* p = (const float4*)(g_s + row * NPIX);
    __half2* oh = (__half2*)(g_at + row * NPIX);
    const int t = threadIdx.x;
    const int lane = t & 31, wid = t >> 5;

    float4 v[4];
    float mx = -1e30f;
    #pragma unroll
    for (int i = 0; i < 4; i++) {
        v[i] = p[t + 256 * i];
        mx = fmaxf(mx, fmaxf(fmaxf(v[i].x, v[i].y), fmaxf(v[i].z, v[i].w)));
    }
    __shared__ float red[8];
    __shared__ float s_mx, s_sum;
    #pragma unroll
    for (int o = 16; o; o >>= 1) mx = fmaxf(mx, __shfl_xor_sync(0xffffffffu, mx, o));
    if (lane == 0) red[wid] = mx;
    __syncthreads();
    if (t == 0) {
        float m = red[0];
        #pragma unroll
        for (int i = 1; i < 8; i++) m = fmaxf(m, red[i]);
        s_mx = m;
    }
    __syncthreads();
    mx = s_mx;

    float sum = 0.f;
    #pragma unroll
    for (int i = 0; i < 4; i++) {
        v[i].x = __expf(v[i].x - mx);
        v[i].y = __expf(v[i].y - mx);
        v[i].z = __expf(v[i].z - mx);
        v[i].w = __expf(v[i].w - mx);
        sum += v[i].x + v[i].y + v[i].z + v[i].w;
    }
    #pragma unroll
    for (int o = 16; o; o >>= 1) sum += __shfl_xor_sync(0xffffffffu, sum, o);
    if (lane == 0) red[wid] = sum;
    __syncthreads();
    if (t == 0) {
        float s = 0.f;
        #pragma unroll
        for (int i = 0; i < 8; i++) s += red[i];
        s_sum = s;
    }
    __syncthreads();
    const float inv = 1.0f / s_sum;

    #pragma unroll
    for (int i = 0; i < 4; i++) {
        int bi = (t + 256 * i) * 2;
        oh[bi + 0] = __halves2half2(__float2half_rn(v[i].x * inv),
                                    __float2half_rn(v[i].y * inv));
        oh[bi + 1] = __halves2half2(__float2half_rn(v[i].z * inv),
                                    __float2half_rn(v[i].w * inv));
    }
}

// ------------------------- launcher -------------------------
extern "C" void kernel_launch(void* const* d_in, const int* in_sizes, int n_in,
                              void* d_out, int out_size)
{
    const float* x     = (const float*)d_in[0];
    const float* gamma = (const float*)d_in[1];
    const float* beta  = (const float*)d_in[2];
    const float* Wq    = (const float*)d_in[3];
    const float* bq    = (const float*)d_in[4];
    const float* Wk    = (const float*)d_in[5];
    const float* bk    = (const float*)d_in[6];
    const float* Wv    = (const float*)d_in[7];
    const float* bv    = (const float*)d_in[8];
    const float* Wo    = (const float*)d_in[9];
    const float* bo    = (const float*)d_in[10];
    float* out = (float*)d_out;

    void* p;
    __half *w_hi, *w_lo, *hnT, *qT_hi, *qT_lo, *kT, *v_hi, *v_lo, *at, *oT;
    float* s_ptr;
    cudaGetSymbolAddress(&p, g_w_hi);  w_hi  = (__half*)p;
    cudaGetSymbolAddress(&p, g_w_lo);  w_lo  = (__half*)p;
    cudaGetSymbolAddress(&p, g_hnT);   hnT   = (__half*)p;
    cudaGetSymbolAddress(&p, g_qT_hi); qT_hi = (__half*)p;
    cudaGetSymbolAddress(&p, g_qT_lo); qT_lo = (__half*)p;
    cudaGetSymbolAddress(&p, g_kT);    kT    = (__half*)p;
    cudaGetSymbolAddress(&p, g_v_hi);  v_hi  = (__half*)p;
    cudaGetSymbolAddress(&p, g_v_lo);  v_lo  = (__half*)p;
    cudaGetSymbolAddress(&p, g_at);    at    = (__half*)p;
    cudaGetSymbolAddress(&p, g_oT);    oT    = (__half*)p;
    cudaGetSymbolAddress(&p, g_s);     s_ptr = (float*)p;

    cudaFuncSetAttribute(gemm_mma<EPI_Q>,  cudaFuncAttributeMaxDynamicSharedMemorySize, SMEM_GEMM);
    cudaFuncSetAttribute(gemm_mma<EPI_K>,  cudaFuncAttributeMaxDynamicSharedMemorySize, SMEM_GEMM);
    cudaFuncSetAttribute(gemm_mma<EPI_V>,  cudaFuncAttributeMaxDynamicSharedMemorySize, SMEM_GEMM);
    cudaFuncSetAttribute(gemm_mma<EPI_S>,  cudaFuncAttributeMaxDynamicSharedMemorySize, SMEM_GEMM);
    cudaFuncSetAttribute(gemm_mma<EPI_AV>, cudaFuncAttributeMaxDynamicSharedMemorySize, SMEM_GEMM);
    cudaFuncSetAttribute(gemm_mma<EPI_P>,  cudaFuncAttributeMaxDynamicSharedMemorySize, SMEM_GEMM);

    const float scale = 1.0f / sqrtf((float)CH);
    const size_t WN = (size_t)CH * CH;

    // 0: all weights fp32 -> fp16 hi/lo
    convert_w4_kernel<<<dim3(WN / 4 / 256, 4), 256>>>(Wq, Wk, Wv, Wo);
    // 1,2: GroupNorm + transpose -> hnT (single fp16)
    gn_stats_kernel<<<dim3(32, BATCH), 256>>>(x);
    tnc_kernel<<<dim3(NPIX / 32, CH / 32, BATCH), 256>>>(x, gamma, beta);

    // 3-5: qkv GEMMs over K=CH, B = hnT [NFOLD, CH]
    dim3 gQKV(NFOLD / 256, CH / 128, 1);
    gemm_mma<EPI_Q><<<gQKV, 512, SMEM_GEMM>>>(
        w_hi + 0 * WN, w_lo + 0 * WN, hnT, CH, 0, 0,
        qT_hi, qT_lo, nullptr, bq, nullptr, scale);
    gemm_mma<EPI_K><<<gQKV, 512, SMEM_GEMM>>>(
        w_hi + 1 * WN, w_lo + 1 * WN, hnT, CH, 0, 0,
        kT, nullptr, nullptr, bk, nullptr, 0.f);
    gemm_mma<EPI_V><<<gQKV, 512, SMEM_GEMM>>>(
        w_hi + 2 * WN, w_lo + 2 * WN, hnT, CH, 0, 0,
        v_hi, v_lo, nullptr, bv, nullptr, 0.f);

    // 6: scores (scale pre-folded into q)
    dim3 gS(NPIX / 256, NPIX / 128, BATCH);
    gemm_mma<EPI_S><<<gS, 512, SMEM_GEMM>>>(
        qT_hi, qT_lo, kT, CH,
        (size_t)NPIX * CH, (size_t)NPIX * CH,
        nullptr, nullptr, s_ptr, nullptr, nullptr, 0.f);

    // 7: softmax -> attn fp16
    softmax_kernel<<<NFOLD, 256>>>();

    // 8: AV: o[c,i] = sum_j v[c,j]*attn[i,j] -> oT single fp16
    dim3 gAV(NPIX / 256, CH / 128, BATCH);
    gemm_mma<EPI_AV><<<gAV, 512, SMEM_GEMM>>>(
        v_hi, v_lo, at, NPIX,
        (size_t)CH * NPIX, (size_t)NPIX * NPIX,
        oT, nullptr, nullptr, nullptr, nullptr, 0.f);

    // 9: proj + bias + residual -> out
    dim3 gP(NFOLD / 256, CH / 128, 1);
    gemm_mma<EPI_P><<<gP, 512, SMEM_GEMM>>>(
        w_hi + 3 * WN, w_lo + 3 * WN, oT, CH, 0, 0,
        nullptr, nullptr, out, bo, x, 0.f);

    (void)in_sizes; (void)n_in; (void)out_size;
}

// round 7
// speedup vs baseline: 5.6496x; 1.5524x over previous
#include <cuda_runtime.h>
#include <cuda_fp16.h>
#include <cstdint>
#include <cmath>

#define BATCH 2
#define CH    512
#define NPIX  4096
#define NFOLD (BATCH * NPIX)     // 8192
#define EPS   1e-6f

// ------------------------- scratch (device globals) -------------------------
static __device__ float2 g_stats[BATCH * 32];
static __device__ __half g_w[4 * CH * CH];                     // q,k,v,o stacked
static __device__ __half g_hnT[(size_t)NFOLD * CH];
static __device__ __half g_qT[(size_t)NFOLD * CH];
static __device__ __half g_kT[(size_t)NFOLD * CH];
static __device__ __half g_v[(size_t)BATCH * CH * NPIX];
static __device__ float  g_s[(size_t)BATCH * NPIX * NPIX];     // 134 MB
static __device__ __half g_at[(size_t)BATCH * NPIX * NPIX];    // 67 MB
static __device__ __half g_oT[(size_t)NFOLD * CH];

// ------------------------- small helpers -------------------------
__device__ __forceinline__ uint32_t smem_u32(const void* p) {
    uint32_t a;
    asm("{ .reg .u64 t; cvta.to.shared.u64 t, %1; cvt.u32.u64 %0, t; }"
        : "=r"(a) : "l"(p));
    return a;
}

__device__ __forceinline__ void cp16(uint32_t s, const void* g) {
    asm volatile("cp.async.cg.shared.global [%0], [%1], 16;" :: "r"(s), "l"(g));
}

#define CP_COMMIT() asm volatile("cp.async.commit_group;" ::: "memory")

#define LDSM4(R, addr) \
    asm volatile("ldmatrix.sync.aligned.m8n8.x4.shared.b16 {%0,%1,%2,%3}, [%4];" \
        : "=r"((R)[0]), "=r"((R)[1]), "=r"((R)[2]), "=r"((R)[3]) : "r"(addr))

#define MMA16816(D, A, B) \
    asm volatile("mma.sync.aligned.m16n8k16.row.col.f32.f16.f16.f32 " \
        "{%0,%1,%2,%3}, {%4,%5,%6,%7}, {%8,%9}, {%0,%1,%2,%3};" \
        : "+f"((D)[0]), "+f"((D)[1]), "+f"((D)[2]), "+f"((D)[3]) \
        : "r"((A)[0]), "r"((A)[1]), "r"((A)[2]), "r"((A)[3]), \
          "r"((B)[0]), "r"((B)[1]))

// ------------------- all W fp32 -> fp16 (one launch, stacked) -------------------
__global__ void __launch_bounds__(256) convert_w4_kernel(
    const float* __restrict__ w0, const float* __restrict__ w1,
    const float* __restrict__ w2, const float* __restrict__ w3)
{
    const float* src = (blockIdx.y == 0) ? w0 : (blockIdx.y == 1) ? w1
                     : (blockIdx.y == 2) ? w2 : w3;
    int i = blockIdx.x * 256 + threadIdx.x;     // float4 index within one W
    float4 v = ((const float4*)src)[i];
    size_t e = (size_t)blockIdx.y * CH * CH + (size_t)i * 4;
    __half2* d = (__half2*)(g_w + e);
    d[0] = __halves2half2(__float2half_rn(v.x), __float2half_rn(v.y));
    d[1] = __halves2half2(__float2half_rn(v.z), __float2half_rn(v.w));
}

// ------------------------- GroupNorm stats -------------------------
__global__ void __launch_bounds__(256) gn_stats_kernel(const float* __restrict__ x)
{
    const int g = blockIdx.x, b = blockIdx.y;
    const size_t base = ((size_t)b * CH + (size_t)g * 16) * NPIX;
    const float4* x4 = (const float4*)(x + base);
    const int n4 = 16 * NPIX / 4;

    float s = 0.f, ss = 0.f;
    for (int i = threadIdx.x; i < n4; i += 256) {
        float4 v = x4[i];
        s  += v.x + v.y + v.z + v.w;
        ss += v.x * v.x + v.y * v.y + v.z * v.z + v.w * v.w;
    }
    __shared__ float rs[8], rss[8];
    #pragma unroll
    for (int o = 16; o; o >>= 1) {
        s  += __shfl_xor_sync(0xffffffffu, s, o);
        ss += __shfl_xor_sync(0xffffffffu, ss, o);
    }
    const int lane = threadIdx.x & 31, wid = threadIdx.x >> 5;
    if (lane == 0) { rs[wid] = s; rss[wid] = ss; }
    __syncthreads();
    if (threadIdx.x == 0) {
        float ts = 0.f, tss = 0.f;
        #pragma unroll
        for (int i = 0; i < 8; i++) { ts += rs[i]; tss += rss[i]; }
        const float inv_n = 1.0f / (16 * NPIX);
        float mean = ts * inv_n;
        float var = tss * inv_n - mean * mean;
        g_stats[b * 32 + g] = make_float2(mean, rsqrtf(var + EPS));
    }
}

// ---------- transpose + normalize + fp16 convert:  x[b,c,n] -> hnT[b*N+n, c] ----------
__global__ void __launch_bounds__(256) tnc_kernel(
    const float* __restrict__ x, const float* __restrict__ gamma,
    const float* __restrict__ beta)
{
    __shared__ float tile[32][33];
    const int b = blockIdx.z;
    const int n0 = blockIdx.x * 32, c0 = blockIdx.y * 32;
    const int tx = threadIdx.x & 31, ty = threadIdx.x >> 5;   // 32 x 8

    #pragma unroll
    for (int j = 0; j < 4; j++) {
        int c = c0 + ty + j * 8;
        float2 st = g_stats[b * 32 + (c >> 4)];
        float gm = gamma[c] * st.y;
        float bt = beta[c] - st.x * gm;
        float v = x[((size_t)(b * CH + c)) * NPIX + n0 + tx];
        tile[ty + j * 8][tx] = v * gm + bt;
    }
    __syncthreads();
    #pragma unroll
    for (int j = 0; j < 4; j++) {
        int n = n0 + ty + j * 8;
        float v = tile[tx][ty + j * 8];
        size_t a = ((size_t)(b * NPIX + n)) * CH + c0 + tx;
        g_hnT[a] = __float2half_rn(v);
    }
}

// ------------------------- mma.sync GEMM (pure fp16) -------------------------
// D[m,n] = sum_k A[m,k]*B[n,k], K-major fp16, fp32 acc.
// CTA: 128(M) x 256(N), K-chunk 32, 4-stage cp.async pipeline, 512 thr (16 warps 4x4).
#define ROWB     80
#define OFF_B    10240
#define STAGE    30720
#define SMEM_GEMM (4 * STAGE)    // 122880; epilogue reuses 66048

enum { EPI_QKV = 0, EPI_S = 1, EPI_AV = 2, EPI_P = 3 };

__device__ __forceinline__ void load_stage(
    uint32_t so,
    const __half* __restrict__ A, const __half* __restrict__ B,
    int K, int k0, int tid)
{
    const int r = tid >> 2, c = tid & 3;       // r 0..127, c = 16B chunk
    const int go = r * K + k0 + c * 8;
    cp16(so + (uint32_t)r * ROWB + c * 16, A + go);
    const uint32_t sB = so + OFF_B + (uint32_t)r * ROWB + c * 16;
    cp16(sB, B + go);
    cp16(sB + 128 * ROWB, B + go + 128 * K);
}

__device__ __forceinline__ void compute_chunk(
    uint32_t so, int wm, int wn, int lane, float acc[2][8][4])
{
    const uint32_t a_base = so + (uint32_t)(wm + (lane & 15)) * ROWB + ((lane >> 4) << 4);
    const uint32_t b_base = so + OFF_B
        + (uint32_t)(wn + ((lane >> 4) << 3) + (lane & 7)) * ROWB
        + (((lane >> 3) & 1) << 4);
    #pragma unroll
    for (int ks = 0; ks < 2; ks++) {
        uint32_t ah[2][4];
        LDSM4(ah[0], a_base + ks * 32);
        LDSM4(ah[1], a_base + ks * 32 + 16 * ROWB);
        #pragma unroll
        for (int np = 0; np < 4; np++) {
            uint32_t bb[4];                     // two n8 fragments
            LDSM4(bb, b_base + ks * 32 + np * 16 * ROWB);
            #pragma unroll
            for (int mt = 0; mt < 2; mt++) {
                MMA16816(acc[mt][np * 2 + 0], ah[mt], bb);
                MMA16816(acc[mt][np * 2 + 1], ah[mt], bb + 2);
            }
        }
    }
}

template<int EPI>
__global__ void __launch_bounds__(512) gemm_mma(
    const __half* __restrict__ A, const __half* __restrict__ B,
    int K, size_t Az, size_t Bz,
    __half* __restrict__ O0, __half* __restrict__ O1, __half* __restrict__ O2,
    float* __restrict__ Ofp,
    const float* __restrict__ b0, const float* __restrict__ b1,
    const float* __restrict__ b2,
    const float* __restrict__ resid, float scale)
{
    extern __shared__ __align__(16) uint8_t gsm[];
    const uint32_t sbase = smem_u32(gsm);
    const int tid = threadIdx.x, lane = tid & 31, wid = tid >> 5;
    const int wm = (wid >> 2) * 32, wn = (wid & 3) * 64;
    const int bz = blockIdx.z;
    const int m0 = blockIdx.y * 128, n0 = blockIdx.x * 256;

    const __half* Ap = A + (size_t)bz * Az + (size_t)m0 * K;
    const __half* Bp = B + (size_t)bz * Bz + (size_t)n0 * K;

    const int NT = K / 32;
    float acc[2][8][4] = {};

    load_stage(sbase + 0 * STAGE, Ap, Bp, K, 0, tid);  CP_COMMIT();
    load_stage(sbase + 1 * STAGE, Ap, Bp, K, 32, tid); CP_COMMIT();
    load_stage(sbase + 2 * STAGE, Ap, Bp, K, 64, tid); CP_COMMIT();

    for (int t = 0; t < NT; t++) {
        asm volatile("cp.async.wait_group 2;" ::: "memory");
        __syncthreads();
        if (t + 3 < NT) {
            load_stage(sbase + (uint32_t)((t + 3) & 3) * STAGE, Ap, Bp, K,
                       (t + 3) * 32, tid);
            CP_COMMIT();
        }
        compute_chunk(sbase + (uint32_t)(t & 3) * STAGE, wm, wn, lane, acc);
    }
    __syncthreads();

    // -------- epilogue: two 128-col halves staged through smem --------
    float* Sf = (float*)gsm;
    const int grp = lane >> 2, tg = lane & 3;
    const int rr = tid >> 5;        // 0..15
    const int cc = tid & 31;        // 0..31

    // QKV: which output this M-block belongs to (uniform over CTA)
    const int wtype = m0 >> 9;              // 0=q, 1=k, 2=v
    const int mloc0 = m0 & (CH - 1);

    #pragma unroll 1
    for (int h = 0; h < 2; h++) {
        __syncthreads();
        if (((wid & 3) >> 1) == h) {
            const int nbase = (wid & 1) * 64;
            #pragma unroll
            for (int mt = 0; mt < 2; mt++) {
                #pragma unroll
                for (int nt = 0; nt < 8; nt++) {
                    int m = wm + mt * 16 + grp;
                    int n = nbase + nt * 8 + tg * 2;
                    Sf[m * 129 + n]           = acc[mt][nt][0];
                    Sf[m * 129 + n + 1]       = acc[mt][nt][1];
                    Sf[(m + 8) * 129 + n]     = acc[mt][nt][2];
                    Sf[(m + 8) * 129 + n + 1] = acc[mt][nt][3];
                }
            }
        }
        __syncthreads();
        const int nglob = n0 + h * 128;

        #pragma unroll 1
        for (int it = 0; it < 8; it++) {
            const int r = rr + it * 16;
            if (EPI == EPI_S) {
                const float* s = &Sf[r * 129 + cc * 4];
                float4 o = make_float4(s[0], s[1], s[2], s[3]);
                *(float4*)&Ofp[((size_t)bz * NPIX + m0 + r) * NPIX + nglob + cc * 4] = o;
            } else if (EPI == EPI_P) {
                const float bv = b0[m0 + r];
                size_t a = ((size_t)((nglob >> 12) * CH + m0 + r)) * NPIX
                         + (nglob & (NPIX - 1)) + cc * 4;
                float4 rd = *(const float4*)&resid[a];
                const float* s = &Sf[r * 129 + cc * 4];
                float4 o = make_float4(s[0] + bv + rd.x, s[1] + bv + rd.y,
                                       s[2] + bv + rd.z, s[3] + bv + rd.w);
                *(float4*)&Ofp[a] = o;
            } else if (EPI == EPI_AV) {
                // D[i=pixel, c=channel] -> oT[(bz*NPIX+i)*CH + c], row-major direct
                size_t a = ((size_t)bz * NPIX + m0 + r) * CH + nglob + cc * 4;
                const float* s = &Sf[r * 129 + cc * 4];
                *(__half2*)&O0[a]     = __halves2half2(__float2half_rn(s[0]),
                                                       __float2half_rn(s[1]));
                *(__half2*)&O0[a + 2] = __halves2half2(__float2half_rn(s[2]),
                                                       __float2half_rn(s[3]));
            } else {    // EPI_QKV
                if (wtype == 2) {
                    // V: direct store v[(b*CH + c)*NPIX + col]
                    const float bv = b2[mloc0 + r];
                    size_t a = ((size_t)((nglob >> 12) * CH + mloc0 + r)) * NPIX
                             + (nglob & (NPIX - 1)) + cc * 4;
                    const float* s = &Sf[r * 129 + cc * 4];
                    *(__half2*)&O2[a]     = __halves2half2(__float2half_rn(s[0] + bv),
                                                           __float2half_rn(s[1] + bv));
                    *(__half2*)&O2[a + 2] = __halves2half2(__float2half_rn(s[2] + bv),
                                                           __float2half_rn(s[3] + bv));
                } else {
                    // Q/K: transposed store O[n*CH + m]
                    __half* Op = (wtype == 0) ? O0 : O1;
                    const float* bp = (wtype == 0) ? b0 : b1;
                    const float sc = (wtype == 0) ? scale : 1.0f;
                    size_t a = ((size_t)nglob + r) * CH + mloc0 + cc * 4;
                    float v0 = (Sf[(cc * 4 + 0) * 129 + r] + bp[mloc0 + cc * 4 + 0]) * sc;
                    float v1 = (Sf[(cc * 4 + 1) * 129 + r] + bp[mloc0 + cc * 4 + 1]) * sc;
                    float v2 = (Sf[(cc * 4 + 2) * 129 + r] + bp[mloc0 + cc * 4 + 2]) * sc;
                    float v3 = (Sf[(cc * 4 + 3) * 129 + r] + bp[mloc0 + cc * 4 + 3]) * sc;
                    *(__half2*)&Op[a]     = __halves2half2(__float2half_rn(v0),
                                                           __float2half_rn(v1));
                    *(__half2*)&Op[a + 2] = __halves2half2(__float2half_rn(v2),
                                                           __float2half_rn(v3));
                }
            }
        }
    }
}

// -------------- softmax rows of g_s -> attn fp16 --------------
__global__ void __launch_bounds__(256) softmax_kernel()
{
    const size_t row = blockIdx.x;       // 0 .. NFOLD-1
    const float4* p = (const float4*)(g_s + row * NPIX);
    __half2* oh = (__half2*)(g_at + row * NPIX);
    const int t = threadIdx.x;
    const int lane = t & 31, wid = t >> 5;

    float4 v[4];
    float mx = -1e30f;
    #pragma unroll
    for (int i = 0; i < 4; i++) {
        v[i] = p[t + 256 * i];
        mx = fmaxf(mx, fmaxf(fmaxf(v[i].x, v[i].y), fmaxf(v[i].z, v[i].w)));
    }
    __shared__ float red[8];
    __shared__ float s_mx, s_sum;
    #pragma unroll
    for (int o = 16; o; o >>= 1) mx = fmaxf(mx, __shfl_xor_sync(0xffffffffu, mx, o));
    if (lane == 0) red[wid] = mx;
    __syncthreads();
    if (t == 0) {
        float m = red[0];
        #pragma unroll
        for (int i = 1; i < 8; i++) m = fmaxf(m, red[i]);
        s_mx = m;
    }
    __syncthreads();
    mx = s_mx;

    float sum = 0.f;
    #pragma unroll
    for (int i = 0; i < 4; i++) {
        v[i].x = __expf(v[i].x - mx);
        v[i].y = __expf(v[i].y - mx);
        v[i].z = __expf(v[i].z - mx);
        v[i].w = __expf(v[i].w - mx);
        sum += v[i].x + v[i].y + v[i].z + v[i].w;
    }
    #pragma unroll
    for (int o = 16; o; o >>= 1) sum += __shfl_xor_sync(0xffffffffu, sum, o);
    if (lane == 0) red[wid] = sum;
    __syncthreads();
    if (t == 0) {
        float s = 0.f;
        #pragma unroll
        for (int i = 0; i < 8; i++) s += red[i];
        s_sum = s;
    }
    __syncthreads();
    const float inv = 1.0f / s_sum;

    #pragma unroll
    for (int i = 0; i < 4; i++) {
        int bi = (t + 256 * i) * 2;
        oh[bi + 0] = __halves2half2(__float2half_rn(v[i].x * inv),
                                    __float2half_rn(v[i].y * inv));
        oh[bi + 1] = __halves2half2(__float2half_rn(v[i].z * inv),
                                    __float2half_rn(v[i].w * inv));
    }
}

// ------------------------- launcher -------------------------
extern "C" void kernel_launch(void* const* d_in, const int* in_sizes, int n_in,
                              void* d_out, int out_size)
{
    const float* x     = (const float*)d_in[0];
    const float* gamma = (const float*)d_in[1];
    const float* beta  = (const float*)d_in[2];
    const float* Wq    = (const float*)d_in[3];
    const float* bq    = (const float*)d_in[4];
    const float* Wk    = (const float*)d_in[5];
    const float* bk    = (const float*)d_in[6];
    const float* Wv    = (const float*)d_in[7];
    const float* bv    = (const float*)d_in[8];
    const float* Wo    = (const float*)d_in[9];
    const float* bo    = (const float*)d_in[10];
    float* out = (float*)d_out;

    void* p;
    __half *w, *hnT, *qT, *kT, *v, *at, *oT;
    float* s_ptr;
    cudaGetSymbolAddress(&p, g_w);    w     = (__half*)p;
    cudaGetSymbolAddress(&p, g_hnT);  hnT   = (__half*)p;
    cudaGetSymbolAddress(&p, g_qT);   qT    = (__half*)p;
    cudaGetSymbolAddress(&p, g_kT);   kT    = (__half*)p;
    cudaGetSymbolAddress(&p, g_v);    v     = (__half*)p;
    cudaGetSymbolAddress(&p, g_at);   at    = (__half*)p;
    cudaGetSymbolAddress(&p, g_oT);   oT    = (__half*)p;
    cudaGetSymbolAddress(&p, g_s);    s_ptr = (float*)p;

    cudaFuncSetAttribute(gemm_mma<EPI_QKV>, cudaFuncAttributeMaxDynamicSharedMemorySize, SMEM_GEMM);
    cudaFuncSetAttribute(gemm_mma<EPI_S>,   cudaFuncAttributeMaxDynamicSharedMemorySize, SMEM_GEMM);
    cudaFuncSetAttribute(gemm_mma<EPI_AV>,  cudaFuncAttributeMaxDynamicSharedMemorySize, SMEM_GEMM);
    cudaFuncSetAttribute(gemm_mma<EPI_P>,   cudaFuncAttributeMaxDynamicSharedMemorySize, SMEM_GEMM);

    const float scale = 1.0f / sqrtf((float)CH);
    const size_t WN = (size_t)CH * CH;

    // 0: weights fp32 -> fp16 (stacked q,k,v,o)
    convert_w4_kernel<<<dim3(WN / 4 / 256, 4), 256>>>(Wq, Wk, Wv, Wo);
    // 1,2: GroupNorm + transpose -> hnT
    gn_stats_kernel<<<dim3(32, BATCH), 256>>>(x);
    tnc_kernel<<<dim3(NPIX / 32, CH / 32, BATCH), 256>>>(x, gamma, beta);

    // 3: fused QKV GEMM: A = stacked W [1536, 512], B = hnT [NFOLD, 512]
    dim3 gQKV(NFOLD / 256, 3 * CH / 128, 1);     // 32 x 12 = 384 CTAs
    gemm_mma<EPI_QKV><<<gQKV, 512, SMEM_GEMM>>>(
        w, hnT, CH, 0, 0,
        qT, kT, v, nullptr, bq, bk, bv, nullptr, scale);

    // 4: scores (scale folded into q)
    dim3 gS(NPIX / 256, NPIX / 128, BATCH);      // 16 x 32 x 2 = 1024 CTAs
    gemm_mma<EPI_S><<<gS, 512, SMEM_GEMM>>>(
        qT, kT, CH, (size_t)NPIX * CH, (size_t)NPIX * CH,
        nullptr, nullptr, nullptr, s_ptr, nullptr, nullptr, nullptr, nullptr, 0.f);

    // 5: softmax -> attn fp16
    softmax_kernel<<<NFOLD, 256>>>();

    // 6: AV: D[i,c] = sum_j attn[i,j] v[c,j] -> oT row-major [NFOLD, CH]
    dim3 gAV(CH / 256, NPIX / 128, BATCH);       // 2 x 32 x 2 = 128 CTAs
    gemm_mma<EPI_AV><<<gAV, 512, SMEM_GEMM>>>(
        at, v, NPIX, (size_t)NPIX * NPIX, (size_t)CH * NPIX,
        oT, nullptr, nullptr, nullptr, nullptr, nullptr, nullptr, nullptr, 0.f);

    // 7: proj + bias + residual -> out
    dim3 gP(NFOLD / 256, CH / 128, 1);           // 32 x 4 = 128 CTAs
    gemm_mma<EPI_P><<<gP, 512, SMEM_GEMM>>>(
        w + 3 * WN, oT, CH, 0, 0,
        nullptr, nullptr, nullptr, out, bo, nullptr, nullptr, x, 0.f);

    (void)in_sizes; (void)n_in; (void)out_size;
}

// round 8
// speedup vs baseline: 6.5092x; 1.1521x over previous
#include <cuda_runtime.h>
#include <cuda_fp16.h>
#include <cstdint>
#include <cmath>

#define BATCH 2
#define CH    512
#define NPIX  4096
#define NFOLD (BATCH * NPIX)     // 8192
#define EPS   1e-6f

// ------------------------- scratch (device globals) -------------------------
static __device__ float2 g_stats[BATCH * 32];
static __device__ __half g_w[4 * CH * CH];                     // q,k,v,o stacked
static __device__ __half g_hnT[(size_t)NFOLD * CH];
static __device__ __half g_qT[(size_t)NFOLD * CH];
static __device__ __half g_kT[(size_t)NFOLD * CH];
static __device__ __half g_v[(size_t)BATCH * CH * NPIX];
static __device__ float  g_s[(size_t)BATCH * NPIX * NPIX];     // 134 MB
static __device__ __half g_at[(size_t)BATCH * NPIX * NPIX];    // 67 MB
static __device__ __half g_oT[(size_t)NFOLD * CH];

// ------------------------- small helpers -------------------------
__device__ __forceinline__ uint32_t smem_u32(const void* p) {
    uint32_t a;
    asm("{ .reg .u64 t; cvta.to.shared.u64 t, %1; cvt.u32.u64 %0, t; }"
        : "=r"(a) : "l"(p));
    return a;
}

__device__ __forceinline__ void cp16(uint32_t s, const void* g) {
    asm volatile("cp.async.cg.shared.global [%0], [%1], 16;" :: "r"(s), "l"(g));
}

#define CP_COMMIT() asm volatile("cp.async.commit_group;" ::: "memory")

#define LDSM4(R, addr) \
    asm volatile("ldmatrix.sync.aligned.m8n8.x4.shared.b16 {%0,%1,%2,%3}, [%4];" \
        : "=r"((R)[0]), "=r"((R)[1]), "=r"((R)[2]), "=r"((R)[3]) : "r"(addr))

#define MMA16816(D, A, B) \
    asm volatile("mma.sync.aligned.m16n8k16.row.col.f32.f16.f16.f32 " \
        "{%0,%1,%2,%3}, {%4,%5,%6,%7}, {%8,%9}, {%0,%1,%2,%3};" \
        : "+f"((D)[0]), "+f"((D)[1]), "+f"((D)[2]), "+f"((D)[3]) \
        : "r"((A)[0]), "r"((A)[1]), "r"((A)[2]), "r"((A)[3]), \
          "r"((B)[0]), "r"((B)[1]))

// ------------------- all W fp32 -> fp16 (one launch, stacked) -------------------
__global__ void __launch_bounds__(256) convert_w4_kernel(
    const float* __restrict__ w0, const float* __restrict__ w1,
    const float* __restrict__ w2, const float* __restrict__ w3)
{
    const float* src = (blockIdx.y == 0) ? w0 : (blockIdx.y == 1) ? w1
                     : (blockIdx.y == 2) ? w2 : w3;
    int i = blockIdx.x * 256 + threadIdx.x;
    float4 v = ((const float4*)src)[i];
    size_t e = (size_t)blockIdx.y * CH * CH + (size_t)i * 4;
    __half2* d = (__half2*)(g_w + e);
    d[0] = __halves2half2(__float2half_rn(v.x), __float2half_rn(v.y));
    d[1] = __halves2half2(__float2half_rn(v.z), __float2half_rn(v.w));
}

// ------------------------- GroupNorm stats -------------------------
__global__ void __launch_bounds__(256) gn_stats_kernel(const float* __restrict__ x)
{
    const int g = blockIdx.x, b = blockIdx.y;
    const size_t base = ((size_t)b * CH + (size_t)g * 16) * NPIX;
    const float4* x4 = (const float4*)(x + base);
    const int n4 = 16 * NPIX / 4;

    float s = 0.f, ss = 0.f;
    for (int i = threadIdx.x; i < n4; i += 256) {
        float4 v = x4[i];
        s  += v.x + v.y + v.z + v.w;
        ss += v.x * v.x + v.y * v.y + v.z * v.z + v.w * v.w;
    }
    __shared__ float rs[8], rss[8];
    #pragma unroll
    for (int o = 16; o; o >>= 1) {
        s  += __shfl_xor_sync(0xffffffffu, s, o);
        ss += __shfl_xor_sync(0xffffffffu, ss, o);
    }
    const int lane = threadIdx.x & 31, wid = threadIdx.x >> 5;
    if (lane == 0) { rs[wid] = s; rss[wid] = ss; }
    __syncthreads();
    if (threadIdx.x == 0) {
        float ts = 0.f, tss = 0.f;
        #pragma unroll
        for (int i = 0; i < 8; i++) { ts += rs[i]; tss += rss[i]; }
        const float inv_n = 1.0f / (16 * NPIX);
        float mean = ts * inv_n;
        float var = tss * inv_n - mean * mean;
        g_stats[b * 32 + g] = make_float2(mean, rsqrtf(var + EPS));
    }
}

// ---------- transpose + normalize + fp16 convert:  x[b,c,n] -> hnT[b*N+n, c] ----------
__global__ void __launch_bounds__(256) tnc_kernel(
    const float* __restrict__ x, const float* __restrict__ gamma,
    const float* __restrict__ beta)
{
    __shared__ float tile[32][33];
    const int b = blockIdx.z;
    const int n0 = blockIdx.x * 32, c0 = blockIdx.y * 32;
    const int tx = threadIdx.x & 31, ty = threadIdx.x >> 5;   // 32 x 8

    #pragma unroll
    for (int j = 0; j < 4; j++) {
        int c = c0 + ty + j * 8;
        float2 st = g_stats[b * 32 + (c >> 4)];
        float gm = gamma[c] * st.y;
        float bt = beta[c] - st.x * gm;
        float v = x[((size_t)(b * CH + c)) * NPIX + n0 + tx];
        tile[ty + j * 8][tx] = v * gm + bt;
    }
    __syncthreads();
    #pragma unroll
    for (int j = 0; j < 4; j++) {
        int n = n0 + ty + j * 8;
        float v = tile[tx][ty + j * 8];
        size_t a = ((size_t)(b * NPIX + n)) * CH + c0 + tx;
        g_hnT[a] = __float2half_rn(v);
    }
}

// ------------------------- mma.sync GEMM (pure fp16, 2 CTA/SM) -------------------------
// D[m,n] = sum_k A[m,k]*B[n,k], K-major fp16, fp32 acc.
// CTA: 128(M) x 128(N), K-chunk 64, XOR-swizzled 128B rows, 3-stage cp.async.
// 512 thr = 16 warps in 4x4, warp tile 32x32. __launch_bounds__(512,2) -> 64 regs.
#define OFF_B    16384
#define STAGE    32768
#define SMEM_GEMM (3 * STAGE)    // 98304; epilogue reuses 66048

enum { EPI_QKV = 0, EPI_S = 1, EPI_AV = 2, EPI_P = 3 };

__device__ __forceinline__ void load_stage(
    uint32_t so, const __half* __restrict__ A, const __half* __restrict__ B,
    int K, int k0, int tid)
{
    #pragma unroll
    for (int j = 0; j < 4; j++) {
        int i = tid + j * 512;                 // 0..2047
        int r = (i >> 3) & 127;                // row within region
        int c = i & 7;                         // 16B unit
        const __half* src = ((j < 2) ? A : B) + r * K + k0 + c * 8;
        uint32_t dst = so + ((j < 2) ? 0u : (uint32_t)OFF_B)
                     + (uint32_t)r * 128 + (uint32_t)((c ^ (r & 7)) << 4);
        cp16(dst, src);
    }
}

__device__ __forceinline__ void compute_chunk(
    uint32_t so, int wm, int wn, int lane, float acc[2][4][4])
{
    const int ra = wm + (lane & 15);
    const int rb = wn + ((lane >> 4) << 3) + (lane & 7);
    const uint32_t a_row = so + (uint32_t)ra * 128;
    const uint32_t b_row = so + OFF_B + (uint32_t)rb * 128;
    const int ua_hi = (lane >> 4);
    const int ub_hi = ((lane >> 3) & 1);

    #pragma unroll
    for (int ks = 0; ks < 4; ks++) {
        uint32_t a0 = a_row + (uint32_t)(((2 * ks + ua_hi) ^ (ra & 7)) << 4);
        uint32_t b0 = b_row + (uint32_t)(((2 * ks + ub_hi) ^ (rb & 7)) << 4);
        uint32_t A0[4], A1[4], B0[4], B1[4];
        LDSM4(A0, a0);
        LDSM4(A1, a0 + 16 * 128);
        LDSM4(B0, b0);
        LDSM4(B1, b0 + 16 * 128);
        MMA16816(acc[0][0], A0, B0);
        MMA16816(acc[0][1], A0, B0 + 2);
        MMA16816(acc[0][2], A0, B1);
        MMA16816(acc[0][3], A0, B1 + 2);
        MMA16816(acc[1][0], A1, B0);
        MMA16816(acc[1][1], A1, B0 + 2);
        MMA16816(acc[1][2], A1, B1);
        MMA16816(acc[1][3], A1, B1 + 2);
    }
}

template<int EPI>
__global__ void __launch_bounds__(512, 2) gemm_mma(
    const __half* __restrict__ A, const __half* __restrict__ B,
    int K, size_t Az, size_t Bz,
    __half* __restrict__ O0, __half* __restrict__ O1, __half* __restrict__ O2,
    float* __restrict__ Ofp,
    const float* __restrict__ b0, const float* __restrict__ b1,
    const float* __restrict__ b2,
    const float* __restrict__ resid, float scale)
{
    extern __shared__ __align__(16) uint8_t gsm[];
    const uint32_t sbase = smem_u32(gsm);
    const int tid = threadIdx.x, lane = tid & 31, wid = tid >> 5;
    const int wm = (wid >> 2) * 32, wn = (wid & 3) * 32;
    const int bz = blockIdx.z;
    const int m0 = blockIdx.y * 128, n0 = blockIdx.x * 128;

    const __half* Ap = A + (size_t)bz * Az + (size_t)m0 * K;
    const __half* Bp = B + (size_t)bz * Bz + (size_t)n0 * K;

    const int NT = K / 64;
    float acc[2][4][4] = {};

    load_stage(sbase + 0 * STAGE, Ap, Bp, K, 0, tid);  CP_COMMIT();
    load_stage(sbase + 1 * STAGE, Ap, Bp, K, 64, tid); CP_COMMIT();

    int s2 = 2, s0 = 0;
    for (int t = 0; t < NT; t++) {
        if (t + 1 < NT) {
            asm volatile("cp.async.wait_group 1;" ::: "memory");
        } else {
            asm volatile("cp.async.wait_group 0;" ::: "memory");
        }
        __syncthreads();
        if (t + 2 < NT) {
            load_stage(sbase + (uint32_t)s2 * STAGE, Ap, Bp, K, (t + 2) * 64, tid);
            CP_COMMIT();
        }
        compute_chunk(sbase + (uint32_t)s0 * STAGE, wm, wn, lane, acc);
        s0++; if (s0 == 3) s0 = 0;
        s2++; if (s2 == 3) s2 = 0;
    }
    __syncthreads();

    // -------- epilogue: single pass through 128x129 fp32 smem --------
    float* Sf = (float*)gsm;
    const int grp = lane >> 2, tg = lane & 3;
    #pragma unroll
    for (int mt = 0; mt < 2; mt++) {
        #pragma unroll
        for (int nf = 0; nf < 4; nf++) {
            int m = wm + mt * 16 + grp;
            int n = wn + nf * 8 + tg * 2;
            Sf[m * 129 + n]           = acc[mt][nf][0];
            Sf[m * 129 + n + 1]       = acc[mt][nf][1];
            Sf[(m + 8) * 129 + n]     = acc[mt][nf][2];
            Sf[(m + 8) * 129 + n + 1] = acc[mt][nf][3];
        }
    }
    __syncthreads();

    const int rr = tid >> 5;        // 0..15
    const int cc = tid & 31;        // 0..31
    const int wtype = m0 >> 9;      // QKV: 0=q,1=k,2=v
    const int mloc0 = m0 & (CH - 1);

    #pragma unroll 1
    for (int it = 0; it < 8; it++) {
        const int r = rr + it * 16;
        if (EPI == EPI_S) {
            const float* s = &Sf[r * 129 + cc * 4];
            float4 o = make_float4(s[0], s[1], s[2], s[3]);
            *(float4*)&Ofp[((size_t)bz * NPIX + m0 + r) * NPIX + n0 + cc * 4] = o;
        } else if (EPI == EPI_P) {
            const float bv = b0[m0 + r];
            size_t a = ((size_t)((n0 >> 12) * CH + m0 + r)) * NPIX
                     + (n0 & (NPIX - 1)) + cc * 4;
            float4 rd = *(const float4*)&resid[a];
            const float* s = &Sf[r * 129 + cc * 4];
            float4 o = make_float4(s[0] + bv + rd.x, s[1] + bv + rd.y,
                                   s[2] + bv + rd.z, s[3] + bv + rd.w);
            *(float4*)&Ofp[a] = o;
        } else if (EPI == EPI_AV) {
            size_t a = ((size_t)bz * NPIX + m0 + r) * CH + n0 + cc * 4;
            const float* s = &Sf[r * 129 + cc * 4];
            *(__half2*)&O0[a]     = __halves2half2(__float2half_rn(s[0]),
                                                   __float2half_rn(s[1]));
            *(__half2*)&O0[a + 2] = __halves2half2(__float2half_rn(s[2]),
                                                   __float2half_rn(s[3]));
        } else {    // EPI_QKV
            if (wtype == 2) {
                const float bv = b2[mloc0 + r];
                size_t a = ((size_t)((n0 >> 12) * CH + mloc0 + r)) * NPIX
                         + (n0 & (NPIX - 1)) + cc * 4;
                const float* s = &Sf[r * 129 + cc * 4];
                *(__half2*)&O2[a]     = __halves2half2(__float2half_rn(s[0] + bv),
                                                       __float2half_rn(s[1] + bv));
                *(__half2*)&O2[a + 2] = __halves2half2(__float2half_rn(s[2] + bv),
                                                       __float2half_rn(s[3] + bv));
            } else {
                __half* Op = (wtype == 0) ? O0 : O1;
                const float* bp = (wtype == 0) ? b0 : b1;
                const float sc = (wtype == 0) ? scale : 1.0f;
                size_t a = ((size_t)n0 + r) * CH + mloc0 + cc * 4;
                float v0 = (Sf[(cc * 4 + 0) * 129 + r] + bp[mloc0 + cc * 4 + 0]) * sc;
                float v1 = (Sf[(cc * 4 + 1) * 129 + r] + bp[mloc0 + cc * 4 + 1]) * sc;
                float v2 = (Sf[(cc * 4 + 2) * 129 + r] + bp[mloc0 + cc * 4 + 2]) * sc;
                float v3 = (Sf[(cc * 4 + 3) * 129 + r] + bp[mloc0 + cc * 4 + 3]) * sc;
                *(__half2*)&Op[a]     = __halves2half2(__float2half_rn(v0),
                                                       __float2half_rn(v1));
                *(__half2*)&Op[a + 2] = __halves2half2(__float2half_rn(v2),
                                                       __float2half_rn(v3));
            }
        }
    }
}

// -------------- softmax rows of g_s -> attn fp16 --------------
__global__ void __launch_bounds__(256) softmax_kernel()
{
    const size_t row = blockIdx.x;       // 0 .. NFOLD-1
    const float4* p = (const float4*)(g_s + row * NPIX);
    __half2* oh = (__half2*)(g_at + row * NPIX);
    const int t = threadIdx.x;
    const int lane = t & 31, wid = t >> 5;

    float4 v[4];
    float mx = -1e30f;
    #pragma unroll
    for (int i = 0; i < 4; i++) {
        v[i] = p[t + 256 * i];
        mx = fmaxf(mx, fmaxf(fmaxf(v[i].x, v[i].y), fmaxf(v[i].z, v[i].w)));
    }
    __shared__ float red[8];
    __shared__ float s_mx, s_sum;
    #pragma unroll
    for (int o = 16; o; o >>= 1) mx = fmaxf(mx, __shfl_xor_sync(0xffffffffu, mx, o));
    if (lane == 0) red[wid] = mx;
    __syncthreads();
    if (t == 0) {
        float m = red[0];
        #pragma unroll
        for (int i = 1; i < 8; i++) m = fmaxf(m, red[i]);
        s_mx = m;
    }
    __syncthreads();
    mx = s_mx;

    float sum = 0.f;
    #pragma unroll
    for (int i = 0; i < 4; i++) {
        v[i].x = __expf(v[i].x - mx);
        v[i].y = __expf(v[i].y - mx);
        v[i].z = __expf(v[i].z - mx);
        v[i].w = __expf(v[i].w - mx);
        sum += v[i].x + v[i].y + v[i].z + v[i].w;
    }
    #pragma unroll
    for (int o = 16; o; o >>= 1) sum += __shfl_xor_sync(0xffffffffu, sum, o);
    if (lane == 0) red[wid] = sum;
    __syncthreads();
    if (t == 0) {
        float s = 0.f;
        #pragma unroll
        for (int i = 0; i < 8; i++) s += red[i];
        s_sum = s;
    }
    __syncthreads();
    const float inv = 1.0f / s_sum;

    #pragma unroll
    for (int i = 0; i < 4; i++) {
        int bi = (t + 256 * i) * 2;
        oh[bi + 0] = __halves2half2(__float2half_rn(v[i].x * inv),
                                    __float2half_rn(v[i].y * inv));
        oh[bi + 1] = __halves2half2(__float2half_rn(v[i].z * inv),
                                    __float2half_rn(v[i].w * inv));
    }
}

// ------------------------- launcher -------------------------
extern "C" void kernel_launch(void* const* d_in, const int* in_sizes, int n_in,
                              void* d_out, int out_size)
{
    const float* x     = (const float*)d_in[0];
    const float* gamma = (const float*)d_in[1];
    const float* beta  = (const float*)d_in[2];
    const float* Wq    = (const float*)d_in[3];
    const float* bq    = (const float*)d_in[4];
    const float* Wk    = (const float*)d_in[5];
    const float* bk    = (const float*)d_in[6];
    const float* Wv    = (const float*)d_in[7];
    const float* bv    = (const float*)d_in[8];
    const float* Wo    = (const float*)d_in[9];
    const float* bo    = (const float*)d_in[10];
    float* out = (float*)d_out;

    void* p;
    __half *w, *hnT, *qT, *kT, *v, *at, *oT;
    float* s_ptr;
    cudaGetSymbolAddress(&p, g_w);    w     = (__half*)p;
    cudaGetSymbolAddress(&p, g_hnT);  hnT   = (__half*)p;
    cudaGetSymbolAddress(&p, g_qT);   qT    = (__half*)p;
    cudaGetSymbolAddress(&p, g_kT);   kT    = (__half*)p;
    cudaGetSymbolAddress(&p, g_v);    v     = (__half*)p;
    cudaGetSymbolAddress(&p, g_at);   at    = (__half*)p;
    cudaGetSymbolAddress(&p, g_oT);   oT    = (__half*)p;
    cudaGetSymbolAddress(&p, g_s);    s_ptr = (float*)p;

    cudaFuncSetAttribute(gemm_mma<EPI_QKV>, cudaFuncAttributeMaxDynamicSharedMemorySize, SMEM_GEMM);
    cudaFuncSetAttribute(gemm_mma<EPI_S>,   cudaFuncAttributeMaxDynamicSharedMemorySize, SMEM_GEMM);
    cudaFuncSetAttribute(gemm_mma<EPI_AV>,  cudaFuncAttributeMaxDynamicSharedMemorySize, SMEM_GEMM);
    cudaFuncSetAttribute(gemm_mma<EPI_P>,   cudaFuncAttributeMaxDynamicSharedMemorySize, SMEM_GEMM);

    const float scale = 1.0f / sqrtf((float)CH);
    const size_t WN = (size_t)CH * CH;

    // weights fp32 -> fp16 (stacked q,k,v,o)
    convert_w4_kernel<<<dim3(WN / 4 / 256, 4), 256>>>(Wq, Wk, Wv, Wo);
    // GroupNorm + transpose -> hnT
    gn_stats_kernel<<<dim3(32, BATCH), 256>>>(x);
    tnc_kernel<<<dim3(NPIX / 32, CH / 32, BATCH), 256>>>(x, gamma, beta);

    // fused QKV GEMM: A = stacked W [1536, 512], B = hnT [NFOLD, 512]
    dim3 gQKV(NFOLD / 128, 3 * CH / 128, 1);     // 64 x 12 = 768 CTAs
    gemm_mma<EPI_QKV><<<gQKV, 512, SMEM_GEMM>>>(
        w, hnT, CH, 0, 0,
        qT, kT, v, nullptr, bq, bk, bv, nullptr, scale);

    // scores (scale folded into q)
    dim3 gS(NPIX / 128, NPIX / 128, BATCH);      // 32 x 32 x 2 = 2048 CTAs
    gemm_mma<EPI_S><<<gS, 512, SMEM_GEMM>>>(
        qT, kT, CH, (size_t)NPIX * CH, (size_t)NPIX * CH,
        nullptr, nullptr, nullptr, s_ptr, nullptr, nullptr, nullptr, nullptr, 0.f);

    // softmax -> attn fp16
    softmax_kernel<<<NFOLD, 256>>>();

    // AV: D[i,c] = sum_j attn[i,j] v[c,j] -> oT row-major [NFOLD, CH]
    dim3 gAV(CH / 128, NPIX / 128, BATCH);       // 4 x 32 x 2 = 256 CTAs
    gemm_mma<EPI_AV><<<gAV, 512, SMEM_GEMM>>>(
        at, v, NPIX, (size_t)NPIX * NPIX, (size_t)CH * NPIX,
        oT, nullptr, nullptr, nullptr, nullptr, nullptr, nullptr, nullptr, 0.f);

    // proj + bias + residual -> out
    dim3 gP(NFOLD / 128, CH / 128, 1);           // 64 x 4 = 256 CTAs
    gemm_mma<EPI_P><<<gP, 512, SMEM_GEMM>>>(
        w + 3 * WN, oT, CH, 0, 0,
        nullptr, nullptr, nullptr, out, bo, nullptr, nullptr, x, 0.f);

    (void)in_sizes; (void)n_in; (void)out_size;
}

// round 9
// speedup vs baseline: 7.0635x; 1.0852x over previous
#include <cuda_runtime.h>
#include <cuda_fp16.h>
#include <cstdint>
#include <cmath>

#define BATCH 2
#define CH    512
#define NPIX  4096
#define NFOLD (BATCH * NPIX)     // 8192
#define EPS   1e-6f

// ------------------------- scratch (device globals) -------------------------
static __device__ float2 g_stats[BATCH * 32];
static __device__ __half g_w[4 * CH * CH];                     // q,k,v,o stacked
static __device__ __half g_hnT[(size_t)NFOLD * CH];
static __device__ __half g_qT[(size_t)NFOLD * CH];
static __device__ __half g_kT[(size_t)NFOLD * CH];
static __device__ __half g_v[(size_t)BATCH * CH * NPIX];
static __device__ float  g_s[(size_t)BATCH * NPIX * NPIX];     // 134 MB
static __device__ __half g_at[(size_t)BATCH * NPIX * NPIX];    // 67 MB
static __device__ __half g_oT[(size_t)NFOLD * CH];

// ------------------------- small helpers -------------------------
__device__ __forceinline__ void cp16(uint32_t s, const void* g) {
    asm volatile("cp.async.cg.shared.global [%0], [%1], 16;" :: "r"(s), "l"(g));
}

#define CP_COMMIT() asm volatile("cp.async.commit_group;" ::: "memory")

#define LDSM4(R, addr) \
    asm volatile("ldmatrix.sync.aligned.m8n8.x4.shared.b16 {%0,%1,%2,%3}, [%4];" \
        : "=r"((R)[0]), "=r"((R)[1]), "=r"((R)[2]), "=r"((R)[3]) : "r"(addr))

#define MMA16816(D, A, B) \
    asm volatile("mma.sync.aligned.m16n8k16.row.col.f32.f16.f16.f32 " \
        "{%0,%1,%2,%3}, {%4,%5,%6,%7}, {%8,%9}, {%0,%1,%2,%3};" \
        : "+f"((D)[0]), "+f"((D)[1]), "+f"((D)[2]), "+f"((D)[3]) \
        : "r"((A)[0]), "r"((A)[1]), "r"((A)[2]), "r"((A)[3]), \
          "r"((B)[0]), "r"((B)[1]))

__device__ __forceinline__ uint32_t smem_u32(const void* p) {
    uint32_t a;
    asm("{ .reg .u64 t; cvta.to.shared.u64 t, %1; cvt.u32.u64 %0, t; }"
        : "=r"(a) : "l"(p));
    return a;
}

// ------------------- all W fp32 -> fp16 (one launch, stacked) -------------------
__global__ void __launch_bounds__(256) convert_w4_kernel(
    const float* __restrict__ w0, const float* __restrict__ w1,
    const float* __restrict__ w2, const float* __restrict__ w3)
{
    const float* src = (blockIdx.y == 0) ? w0 : (blockIdx.y == 1) ? w1
                     : (blockIdx.y == 2) ? w2 : w3;
    int i = blockIdx.x * 256 + threadIdx.x;
    float4 v = ((const float4*)src)[i];
    size_t e = (size_t)blockIdx.y * CH * CH + (size_t)i * 4;
    __half2* d = (__half2*)(g_w + e);
    d[0] = __halves2half2(__float2half_rn(v.x), __float2half_rn(v.y));
    d[1] = __halves2half2(__float2half_rn(v.z), __float2half_rn(v.w));
}

// ------------------------- GroupNorm stats -------------------------
__global__ void __launch_bounds__(256) gn_stats_kernel(const float* __restrict__ x)
{
    const int g = blockIdx.x, b = blockIdx.y;
    const size_t base = ((size_t)b * CH + (size_t)g * 16) * NPIX;
    const float4* x4 = (const float4*)(x + base);
    const int n4 = 16 * NPIX / 4;

    float s = 0.f, ss = 0.f;
    for (int i = threadIdx.x; i < n4; i += 256) {
        float4 v = x4[i];
        s  += v.x + v.y + v.z + v.w;
        ss += v.x * v.x + v.y * v.y + v.z * v.z + v.w * v.w;
    }
    __shared__ float rs[8], rss[8];
    #pragma unroll
    for (int o = 16; o; o >>= 1) {
        s  += __shfl_xor_sync(0xffffffffu, s, o);
        ss += __shfl_xor_sync(0xffffffffu, ss, o);
    }
    const int lane = threadIdx.x & 31, wid = threadIdx.x >> 5;
    if (lane == 0) { rs[wid] = s; rss[wid] = ss; }
    __syncthreads();
    if (threadIdx.x == 0) {
        float ts = 0.f, tss = 0.f;
        #pragma unroll
        for (int i = 0; i < 8; i++) { ts += rs[i]; tss += rss[i]; }
        const float inv_n = 1.0f / (16 * NPIX);
        float mean = ts * inv_n;
        float var = tss * inv_n - mean * mean;
        g_stats[b * 32 + g] = make_float2(mean, rsqrtf(var + EPS));
    }
}

// ---------- transpose + normalize + fp16 convert:  x[b,c,n] -> hnT[b*N+n, c] ----------
__global__ void __launch_bounds__(256) tnc_kernel(
    const float* __restrict__ x, const float* __restrict__ gamma,
    const float* __restrict__ beta)
{
    __shared__ float tile[32][33];
    const int b = blockIdx.z;
    const int n0 = blockIdx.x * 32, c0 = blockIdx.y * 32;
    const int tx = threadIdx.x & 31, ty = threadIdx.x >> 5;   // 32 x 8

    #pragma unroll
    for (int j = 0; j < 4; j++) {
        int c = c0 + ty + j * 8;
        float2 st = g_stats[b * 32 + (c >> 4)];
        float gm = gamma[c] * st.y;
        float bt = beta[c] - st.x * gm;
        float v = x[((size_t)(b * CH + c)) * NPIX + n0 + tx];
        tile[ty + j * 8][tx] = v * gm + bt;
    }
    __syncthreads();
    #pragma unroll
    for (int j = 0; j < 4; j++) {
        int n = n0 + ty + j * 8;
        float v = tile[tx][ty + j * 8];
        size_t a = ((size_t)(b * NPIX + n)) * CH + c0 + tx;
        g_hnT[a] = __float2half_rn(v);
    }
}

// ------------------------- mma.sync GEMM (fp16, 8 warps, 64x32 warp tile) -------------------------
// D[m,n] = sum_k A[m,k]*B[n,k], K-major fp16, fp32 acc.
// CTA: 128(M) x 128(N), K-chunk 64, XOR-swizzled 128B rows, 3-stage cp.async.
// 256 thr = 8 warps in 2(M) x 4(N); warp tile 64x32. __launch_bounds__(256,2).
#define OFF_B    16384
#define STAGE    32768
#define SMEM_GEMM (3 * STAGE)    // 98304; epilogue reuses 66048

enum { EPI_QKV = 0, EPI_S = 1, EPI_AV = 2, EPI_P = 3 };

__device__ __forceinline__ void load_stage(
    uint32_t so, const __half* __restrict__ A, const __half* __restrict__ B,
    int K, int k0, int tid)
{
    #pragma unroll
    for (int j = 0; j < 8; j++) {
        int i = tid + j * 256;                 // 0..2047
        int r = (i >> 3) & 127;                // row within region
        int c = i & 7;                         // 16B unit
        const __half* src = ((j < 4) ? A : B) + r * K + k0 + c * 8;
        uint32_t dst = so + ((j < 4) ? 0u : (uint32_t)OFF_B)
                     + (uint32_t)r * 128 + (uint32_t)((c ^ (r & 7)) << 4);
        cp16(dst, src);
    }
}

__device__ __forceinline__ void compute_chunk(
    uint32_t so, int wm, int wn, int lane, float acc[4][4][4])
{
    const int ra = wm + (lane & 15);
    const int rb = wn + ((lane >> 4) << 3) + (lane & 7);
    const uint32_t a_row = so + (uint32_t)ra * 128;
    const uint32_t b_row = so + OFF_B + (uint32_t)rb * 128;
    const int ua = (lane >> 4);
    const int ub = ((lane >> 3) & 1);

    #pragma unroll
    for (int ks = 0; ks < 4; ks++) {
        const uint32_t a_sw = (uint32_t)(((2 * ks + ua) ^ (ra & 7)) << 4);
        const uint32_t b_sw = (uint32_t)(((2 * ks + ub) ^ (rb & 7)) << 4);
        uint32_t A0[4], A1[4], A2[4], A3[4], B0[4], B1[4];
        LDSM4(A0, a_row + a_sw);
        LDSM4(A1, a_row + a_sw + 16 * 128);
        LDSM4(A2, a_row + a_sw + 32 * 128);
        LDSM4(A3, a_row + a_sw + 48 * 128);
        LDSM4(B0, b_row + b_sw);
        LDSM4(B1, b_row + b_sw + 16 * 128);
        MMA16816(acc[0][0], A0, B0);  MMA16816(acc[0][1], A0, B0 + 2);
        MMA16816(acc[0][2], A0, B1);  MMA16816(acc[0][3], A0, B1 + 2);
        MMA16816(acc[1][0], A1, B0);  MMA16816(acc[1][1], A1, B0 + 2);
        MMA16816(acc[1][2], A1, B1);  MMA16816(acc[1][3], A1, B1 + 2);
        MMA16816(acc[2][0], A2, B0);  MMA16816(acc[2][1], A2, B0 + 2);
        MMA16816(acc[2][2], A2, B1);  MMA16816(acc[2][3], A2, B1 + 2);
        MMA16816(acc[3][0], A3, B0);  MMA16816(acc[3][1], A3, B0 + 2);
        MMA16816(acc[3][2], A3, B1);  MMA16816(acc[3][3], A3, B1 + 2);
    }
}

template<int EPI>
__global__ void __launch_bounds__(256, 2) gemm_mma(
    const __half* __restrict__ A, const __half* __restrict__ B,
    int K, size_t Az, size_t Bz,
    __half* __restrict__ O0, __half* __restrict__ O1, __half* __restrict__ O2,
    float* __restrict__ Ofp,
    const float* __restrict__ b0, const float* __restrict__ b1,
    const float* __restrict__ b2,
    const float* __restrict__ resid, float scale)
{
    extern __shared__ __align__(16) uint8_t gsm[];
    const uint32_t sbase = smem_u32(gsm);
    const int tid = threadIdx.x, lane = tid & 31, wid = tid >> 5;
    const int wm = (wid >> 2) * 64, wn = (wid & 3) * 32;
    const int bz = blockIdx.z;
    const int m0 = blockIdx.y * 128, n0 = blockIdx.x * 128;

    const __half* Ap = A + (size_t)bz * Az + (size_t)m0 * K;
    const __half* Bp = B + (size_t)bz * Bz + (size_t)n0 * K;

    const int NT = K / 64;
    float acc[4][4][4] = {};

    load_stage(sbase + 0 * STAGE, Ap, Bp, K, 0, tid);  CP_COMMIT();
    load_stage(sbase + 1 * STAGE, Ap, Bp, K, 64, tid); CP_COMMIT();

    int s2 = 2, s0 = 0;
    for (int t = 0; t < NT; t++) {
        if (t + 1 < NT) {
            asm volatile("cp.async.wait_group 1;" ::: "memory");
        } else {
            asm volatile("cp.async.wait_group 0;" ::: "memory");
        }
        __syncthreads();
        if (t + 2 < NT) {
            load_stage(sbase + (uint32_t)s2 * STAGE, Ap, Bp, K, (t + 2) * 64, tid);
            CP_COMMIT();
        }
        compute_chunk(sbase + (uint32_t)s0 * STAGE, wm, wn, lane, acc);
        s0++; if (s0 == 3) s0 = 0;
        s2++; if (s2 == 3) s2 = 0;
    }
    __syncthreads();

    // -------- epilogue: single pass through 128x129 fp32 smem --------
    float* Sf = (float*)gsm;
    const int grp = lane >> 2, tg = lane & 3;
    #pragma unroll
    for (int mt = 0; mt < 4; mt++) {
        #pragma unroll
        for (int nf = 0; nf < 4; nf++) {
            int m = wm + mt * 16 + grp;
            int n = wn + nf * 8 + tg * 2;
            Sf[m * 129 + n]           = acc[mt][nf][0];
            Sf[m * 129 + n + 1]       = acc[mt][nf][1];
            Sf[(m + 8) * 129 + n]     = acc[mt][nf][2];
            Sf[(m + 8) * 129 + n + 1] = acc[mt][nf][3];
        }
    }
    __syncthreads();

    const int rr = tid >> 5;        // 0..7
    const int cc = tid & 31;        // 0..31
    const int wtype = m0 >> 9;      // QKV: 0=q,1=k,2=v
    const int mloc0 = m0 & (CH - 1);

    #pragma unroll 1
    for (int it = 0; it < 16; it++) {
        const int r = rr + it * 8;
        if (EPI == EPI_S) {
            const float* s = &Sf[r * 129 + cc * 4];
            float4 o = make_float4(s[0], s[1], s[2], s[3]);
            *(float4*)&Ofp[((size_t)bz * NPIX + m0 + r) * NPIX + n0 + cc * 4] = o;
        } else if (EPI == EPI_P) {
            const float bv = b0[m0 + r];
            size_t a = ((size_t)((n0 >> 12) * CH + m0 + r)) * NPIX
                     + (n0 & (NPIX - 1)) + cc * 4;
            float4 rd = *(const float4*)&resid[a];
            const float* s = &Sf[r * 129 + cc * 4];
            float4 o = make_float4(s[0] + bv + rd.x, s[1] + bv + rd.y,
                                   s[2] + bv + rd.z, s[3] + bv + rd.w);
            *(float4*)&Ofp[a] = o;
        } else if (EPI == EPI_AV) {
            size_t a = ((size_t)bz * NPIX + m0 + r) * CH + n0 + cc * 4;
            const float* s = &Sf[r * 129 + cc * 4];
            *(__half2*)&O0[a]     = __halves2half2(__float2half_rn(s[0]),
                                                   __float2half_rn(s[1]));
            *(__half2*)&O0[a + 2] = __halves2half2(__float2half_rn(s[2]),
                                                   __float2half_rn(s[3]));
        } else {    // EPI_QKV
            if (wtype == 2) {
                const float bv = b2[mloc0 + r];
                size_t a = ((size_t)((n0 >> 12) * CH + mloc0 + r)) * NPIX
                         + (n0 & (NPIX - 1)) + cc * 4;
                const float* s = &Sf[r * 129 + cc * 4];
                *(__half2*)&O2[a]     = __halves2half2(__float2half_rn(s[0] + bv),
                                                       __float2half_rn(s[1] + bv));
                *(__half2*)&O2[a + 2] = __halves2half2(__float2half_rn(s[2] + bv),
                                                       __float2half_rn(s[3] + bv));
            } else {
                __half* Op = (wtype == 0) ? O0 : O1;
                const float* bp = (wtype == 0) ? b0 : b1;
                const float sc = (wtype == 0) ? scale : 1.0f;
                size_t a = ((size_t)n0 + r) * CH + mloc0 + cc * 4;
                float v0 = (Sf[(cc * 4 + 0) * 129 + r] + bp[mloc0 + cc * 4 + 0]) * sc;
                float v1 = (Sf[(cc * 4 + 1) * 129 + r] + bp[mloc0 + cc * 4 + 1]) * sc;
                float v2 = (Sf[(cc * 4 + 2) * 129 + r] + bp[mloc0 + cc * 4 + 2]) * sc;
                float v3 = (Sf[(cc * 4 + 3) * 129 + r] + bp[mloc0 + cc * 4 + 3]) * sc;
                *(__half2*)&Op[a]     = __halves2half2(__float2half_rn(v0),
                                                       __float2half_rn(v1));
                *(__half2*)&Op[a + 2] = __halves2half2(__float2half_rn(v2),
                                                       __float2half_rn(v3));
            }
        }
    }
}

// -------------- softmax rows of g_s -> attn fp16 --------------
__global__ void __launch_bounds__(256) softmax_kernel()
{
    const size_t row = blockIdx.x;       // 0 .. NFOLD-1
    const float4* p = (const float4*)(g_s + row * NPIX);
    __half2* oh = (__half2*)(g_at + row * NPIX);
    const int t = threadIdx.x;
    const int lane = t & 31, wid = t >> 5;

    float4 v[4];
    float mx = -1e30f;
    #pragma unroll
    for (int i = 0; i < 4; i++) {
        v[i] = p[t + 256 * i];
        mx = fmaxf(mx, fmaxf(fmaxf(v[i].x, v[i].y), fmaxf(v[i].z, v[i].w)));
    }
    __shared__ float red[8];
    __shared__ float s_mx, s_sum;
    #pragma unroll
    for (int o = 16; o; o >>= 1) mx = fmaxf(mx, __shfl_xor_sync(0xffffffffu, mx, o));
    if (lane == 0) red[wid] = mx;
    __syncthreads();
    if (t == 0) {
        float m = red[0];
        #pragma unroll
        for (int i = 1; i < 8; i++) m = fmaxf(m, red[i]);
        s_mx = m;
    }
    __syncthreads();
    mx = s_mx;

    float sum = 0.f;
    #pragma unroll
    for (int i = 0; i < 4; i++) {
        v[i].x = __expf(v[i].x - mx);
        v[i].y = __expf(v[i].y - mx);
        v[i].z = __expf(v[i].z - mx);
        v[i].w = __expf(v[i].w - mx);
        sum += v[i].x + v[i].y + v[i].z + v[i].w;
    }
    #pragma unroll
    for (int o = 16; o; o >>= 1) sum += __shfl_xor_sync(0xffffffffu, sum, o);
    if (lane == 0) red[wid] = sum;
    __syncthreads();
    if (t == 0) {
        float s = 0.f;
        #pragma unroll
        for (int i = 0; i < 8; i++) s += red[i];
        s_sum = s;
    }
    __syncthreads();
    const float inv = 1.0f / s_sum;

    #pragma unroll
    for (int i = 0; i < 4; i++) {
        int bi = (t + 256 * i) * 2;
        oh[bi + 0] = __halves2half2(__float2half_rn(v[i].x * inv),
                                    __float2half_rn(v[i].y * inv));
        oh[bi + 1] = __halves2half2(__float2half_rn(v[i].z * inv),
                                    __float2half_rn(v[i].w * inv));
    }
}

// ------------------------- launcher -------------------------
extern "C" void kernel_launch(void* const* d_in, const int* in_sizes, int n_in,
                              void* d_out, int out_size)
{
    const float* x     = (const float*)d_in[0];
    const float* gamma = (const float*)d_in[1];
    const float* beta  = (const float*)d_in[2];
    const float* Wq    = (const float*)d_in[3];
    const float* bq    = (const float*)d_in[4];
    const float* Wk    = (const float*)d_in[5];
    const float* bk    = (const float*)d_in[6];
    const float* Wv    = (const float*)d_in[7];
    const float* bv    = (const float*)d_in[8];
    const float* Wo    = (const float*)d_in[9];
    const float* bo    = (const float*)d_in[10];
    float* out = (float*)d_out;

    void* p;
    __half *w, *hnT, *qT, *kT, *v, *at, *oT;
    float* s_ptr;
    cudaGetSymbolAddress(&p, g_w);    w     = (__half*)p;
    cudaGetSymbolAddress(&p, g_hnT);  hnT   = (__half*)p;
    cudaGetSymbolAddress(&p, g_qT);   qT    = (__half*)p;
    cudaGetSymbolAddress(&p, g_kT);   kT    = (__half*)p;
    cudaGetSymbolAddress(&p, g_v);    v     = (__half*)p;
    cudaGetSymbolAddress(&p, g_at);   at    = (__half*)p;
    cudaGetSymbolAddress(&p, g_oT);   oT    = (__half*)p;
    cudaGetSymbolAddress(&p, g_s);    s_ptr = (float*)p;

    cudaFuncSetAttribute(gemm_mma<EPI_QKV>, cudaFuncAttributeMaxDynamicSharedMemorySize, SMEM_GEMM);
    cudaFuncSetAttribute(gemm_mma<EPI_S>,   cudaFuncAttributeMaxDynamicSharedMemorySize, SMEM_GEMM);
    cudaFuncSetAttribute(gemm_mma<EPI_AV>,  cudaFuncAttributeMaxDynamicSharedMemorySize, SMEM_GEMM);
    cudaFuncSetAttribute(gemm_mma<EPI_P>,   cudaFuncAttributeMaxDynamicSharedMemorySize, SMEM_GEMM);

    const float scale = 1.0f / sqrtf((float)CH);
    const size_t WN = (size_t)CH * CH;

    // weights fp32 -> fp16 (stacked q,k,v,o)
    convert_w4_kernel<<<dim3(WN / 4 / 256, 4), 256>>>(Wq, Wk, Wv, Wo);
    // GroupNorm + transpose -> hnT
    gn_stats_kernel<<<dim3(32, BATCH), 256>>>(x);
    tnc_kernel<<<dim3(NPIX / 32, CH / 32, BATCH), 256>>>(x, gamma, beta);

    // fused QKV GEMM: A = stacked W [1536, 512], B = hnT [NFOLD, 512]
    dim3 gQKV(NFOLD / 128, 3 * CH / 128, 1);     // 64 x 12 = 768 CTAs
    gemm_mma<EPI_QKV><<<gQKV, 256, SMEM_GEMM>>>(
        w, hnT, CH, 0, 0,
        qT, kT, v, nullptr, bq, bk, bv, nullptr, scale);

    // scores (scale folded into q)
    dim3 gS(NPIX / 128, NPIX / 128, BATCH);      // 32 x 32 x 2 = 2048 CTAs
    gemm_mma<EPI_S><<<gS, 256, SMEM_GEMM>>>(
        qT, kT, CH, (size_t)NPIX * CH, (size_t)NPIX * CH,
        nullptr, nullptr, nullptr, s_ptr, nullptr, nullptr, nullptr, nullptr, 0.f);

    // softmax -> attn fp16
    softmax_kernel<<<NFOLD, 256>>>();

    // AV: D[i,c] = sum_j attn[i,j] v[c,j] -> oT row-major [NFOLD, CH]
    dim3 gAV(CH / 128, NPIX / 128, BATCH);       // 4 x 32 x 2 = 256 CTAs
    gemm_mma<EPI_AV><<<gAV, 256, SMEM_GEMM>>>(
        at, v, NPIX, (size_t)NPIX * NPIX, (size_t)CH * NPIX,
        oT, nullptr, nullptr, nullptr, nullptr, nullptr, nullptr, nullptr, 0.f);

    // proj + bias + residual -> out
    dim3 gP(NFOLD / 128, CH / 128, 1);           // 64 x 4 = 256 CTAs
    gemm_mma<EPI_P><<<gP, 256, SMEM_GEMM>>>(
        w + 3 * WN, oT, CH, 0, 0,
        nullptr, nullptr, nullptr, out, bo, nullptr, nullptr, x, 0.f);

    (void)in_sizes; (void)n_in; (void)out_size;
}